// round 2
// baseline (speedup 1.0000x reference)
#include <cuda_runtime.h>
#include <math.h>

// Problem dims (fixed by the dataset)
#define BT  4096     // B*T tokens
#define DIM 1024     // model dim
#define FF  4096     // mlp dim
#define NH  8        // heads
#define DH  128      // head dim
#define NB  2        // batch
#define TT  2048     // seq len

// ---------------- scratch (device globals; no allocation allowed) ----------
__device__ float g_xn  [BT * DIM];
__device__ float g_q   [BT * DIM];
__device__ float g_k   [BT * DIM];
__device__ float g_v   [BT * DIM];
__device__ float g_beta[BT * NH];
__device__ float g_alph[BT * NH];
__device__ float g_attn[BT * DIM];
__device__ float g_x1  [BT * DIM];
__device__ float g_xn2 [BT * DIM];
__device__ float g_hg  [BT * FF];
__device__ float g_hu  [BT * FF];

// ---------------- rmsnorm: one block per row, 256 thr x 4 elems ------------
__global__ __launch_bounds__(256) void rmsnorm_kernel(const float* __restrict__ in,
                                                      float* __restrict__ out)
{
    int row = blockIdx.x;
    int i   = threadIdx.x * 4;
    const float* r = in + (size_t)row * DIM;
    float4 xv = *(const float4*)&r[i];
    float ss = xv.x*xv.x + xv.y*xv.y + xv.z*xv.z + xv.w*xv.w;

    #pragma unroll
    for (int o = 16; o > 0; o >>= 1) ss += __shfl_xor_sync(0xffffffffu, ss, o);
    __shared__ float sbuf[8];
    int w = threadIdx.x >> 5;
    if ((threadIdx.x & 31) == 0) sbuf[w] = ss;
    __syncthreads();
    float tot = sbuf[0]+sbuf[1]+sbuf[2]+sbuf[3]+sbuf[4]+sbuf[5]+sbuf[6]+sbuf[7];
    float scale = rsqrtf(tot * (1.0f / DIM) + 1e-6f);

    float4 ov;
    ov.x = xv.x*scale; ov.y = xv.y*scale; ov.z = xv.z*scale; ov.w = xv.w*scale;
    *(float4*)&out[(size_t)row * DIM + i] = ov;
}

// ---------------- fp32 tiled GEMM: C[M,N] = A[M,K] @ B[K,N] (+Res) ---------
// BM=128, BN=64, BK=16, 256 threads, 8x4 per-thread micro-tile.
// Requires M%128==0, N%64==0, K%16==0 (true for all calls here).
__global__ __launch_bounds__(256) void gemm_kernel(const float* __restrict__ A,
                                                   const float* __restrict__ B,
                                                   const float* __restrict__ Res,
                                                   float* __restrict__ C,
                                                   int M, int N, int K)
{
    const int BM = 128, BN = 64, BK = 16;
    __shared__ __align__(16) float As[BK][BM + 4];   // stride 132 floats (16B-aligned)
    __shared__ __align__(16) float Bs[BK][BN];

    int t  = threadIdx.x;
    int tx = t & 15;            // 0..15 -> N
    int ty = t >> 4;            // 0..15 -> M (rows of 8)
    int bm = blockIdx.y * BM;
    int bn = blockIdx.x * BN;

    // A tile load: 128 rows x 16 cols = 2048 floats; each thread 8 contiguous (2 float4)
    int aRow = t >> 1;          // 0..127
    int aCol = (t & 1) * 8;     // 0 or 8
    // B tile load: 16 rows x 64 cols = 1024 floats; each thread 1 float4
    int bRow = t >> 4;          // 0..15
    int bCol = (t & 15) * 4;    // 0..60

    float acc[8][4] = {};

    for (int k0 = 0; k0 < K; k0 += BK) {
        const float* ap = &A[(size_t)(bm + aRow) * K + k0 + aCol];
        float4 a0 = *(const float4*)&ap[0];
        float4 a1 = *(const float4*)&ap[4];
        As[aCol + 0][aRow] = a0.x;
        As[aCol + 1][aRow] = a0.y;
        As[aCol + 2][aRow] = a0.z;
        As[aCol + 3][aRow] = a0.w;
        As[aCol + 4][aRow] = a1.x;
        As[aCol + 5][aRow] = a1.y;
        As[aCol + 6][aRow] = a1.z;
        As[aCol + 7][aRow] = a1.w;
        *(float4*)&Bs[bRow][bCol] = *(const float4*)&B[(size_t)(k0 + bRow) * N + bn + bCol];
        __syncthreads();

        #pragma unroll
        for (int kk = 0; kk < BK; ++kk) {
            float4 aLo = *(const float4*)&As[kk][ty * 8];
            float4 aHi = *(const float4*)&As[kk][ty * 8 + 4];
            float4 b   = *(const float4*)&Bs[kk][tx * 4];
            float ar[8] = {aLo.x, aLo.y, aLo.z, aLo.w, aHi.x, aHi.y, aHi.z, aHi.w};
            float br[4] = {b.x, b.y, b.z, b.w};
            #pragma unroll
            for (int i = 0; i < 8; ++i)
                #pragma unroll
                for (int j = 0; j < 4; ++j)
                    acc[i][j] = fmaf(ar[i], br[j], acc[i][j]);
        }
        __syncthreads();
    }

    #pragma unroll
    for (int i = 0; i < 8; ++i) {
        int row = bm + ty * 8 + i;
        size_t off = (size_t)row * N + bn + tx * 4;
        float4 o;
        if (Res) {
            float4 rv = *(const float4*)&Res[off];
            o.x = acc[i][0] + rv.x; o.y = acc[i][1] + rv.y;
            o.z = acc[i][2] + rv.z; o.w = acc[i][3] + rv.w;
        } else {
            o.x = acc[i][0]; o.y = acc[i][1]; o.z = acc[i][2]; o.w = acc[i][3];
        }
        *(float4*)&C[off] = o;
    }
}

// ---------------- beta/alpha: sigmoid(xn @ wb), sigmoid(xn @ wg) -----------
__global__ __launch_bounds__(256) void ba_kernel(const float* __restrict__ xn,
                                                 const float* __restrict__ wb,
                                                 const float* __restrict__ wg,
                                                 float* __restrict__ beta,
                                                 float* __restrict__ alph)
{
    __shared__ __align__(16) float xr[DIM];
    int tok = blockIdx.x;
    int t = threadIdx.x;
    *(float4*)&xr[t * 4] = *(const float4*)&xn[(size_t)tok * DIM + t * 4];
    __syncthreads();

    int w = t >> 5, lane = t & 31;
    float ab = 0.f, aa = 0.f;
    #pragma unroll 4
    for (int d = lane; d < DIM; d += 32) {
        float xv = xr[d];
        ab = fmaf(xv, wb[d * NH + w], ab);
        aa = fmaf(xv, wg[d * NH + w], aa);
    }
    #pragma unroll
    for (int o = 16; o > 0; o >>= 1) {
        ab += __shfl_xor_sync(0xffffffffu, ab, o);
        aa += __shfl_xor_sync(0xffffffffu, aa, o);
    }
    if (lane == 0) {
        beta[tok * NH + w] = 1.0f / (1.0f + expf(-ab));
        alph[tok * NH + w] = 1.0f / (1.0f + expf(-aa));
    }
}

// ---------------- activations: silu + per-head l2norm on q,k; silu on v ----
__global__ __launch_bounds__(128) void act_kernel(float* __restrict__ q,
                                                  float* __restrict__ k,
                                                  float* __restrict__ v)
{
    int tok = blockIdx.x, h = blockIdx.y, t = threadIdx.x;
    size_t idx = (size_t)tok * DIM + h * DH + t;
    float qv = q[idx], kv = k[idx], vv = v[idx];
    float qs = qv / (1.0f + expf(-qv));
    float ks = kv / (1.0f + expf(-kv));
    float vs = vv / (1.0f + expf(-vv));

    float a = qs * qs, b = ks * ks;
    #pragma unroll
    for (int o = 16; o > 0; o >>= 1) {
        a += __shfl_xor_sync(0xffffffffu, a, o);
        b += __shfl_xor_sync(0xffffffffu, b, o);
    }
    __shared__ float sq[4], sk[4];
    int w = t >> 5;
    if ((t & 31) == 0) { sq[w] = a; sk[w] = b; }
    __syncthreads();
    float qsum = sq[0] + sq[1] + sq[2] + sq[3];
    float ksum = sk[0] + sk[1] + sk[2] + sk[3];

    q[idx] = qs * rsqrtf(qsum + 1e-6f);
    k[idx] = ks * rsqrtf(ksum + 1e-6f);
    v[idx] = vs;
}

// ---------------- gated delta-rule scan: 16 blocks (b,h), S in registers ---
__global__ __launch_bounds__(128) void scan_kernel(const float* __restrict__ q,
                                                   const float* __restrict__ k,
                                                   const float* __restrict__ v,
                                                   const float* __restrict__ beta,
                                                   const float* __restrict__ alph,
                                                   const float* __restrict__ state_in,
                                                   float* __restrict__ attn,
                                                   float* __restrict__ state_out)
{
    int bh = blockIdx.x;         // b*NH + h
    int b  = bh >> 3;
    int h  = bh & 7;
    int vl = threadIdx.x;        // this thread owns state column v = vl

    float S[DH];                 // S[k][vl]
    const float* st = state_in + (size_t)bh * DH * DH;
    #pragma unroll
    for (int kk = 0; kk < DH; ++kk) S[kk] = st[kk * DH + vl];

    __shared__ __align__(16) float sk[DH];
    __shared__ __align__(16) float sq[DH];

    for (int t = 0; t < TT; ++t) {
        int tok = b * TT + t;
        size_t base = (size_t)tok * DIM + h * DH;
        float vv = v[base + vl];
        sk[vl] = k[base + vl];
        sq[vl] = q[base + vl];
        float bt = beta[tok * NH + h];
        float at = alph[tok * NH + h];
        __syncthreads();

        // pred = alpha * (k . S_old[:,vl])
        float p0 = 0.f, p1 = 0.f, p2 = 0.f, p3 = 0.f;
        #pragma unroll
        for (int kk = 0; kk < DH; kk += 4) {
            float4 k4 = *(const float4*)&sk[kk];
            p0 = fmaf(k4.x, S[kk + 0], p0);
            p1 = fmaf(k4.y, S[kk + 1], p1);
            p2 = fmaf(k4.z, S[kk + 2], p2);
            p3 = fmaf(k4.w, S[kk + 3], p3);
        }
        float pred = at * ((p0 + p1) + (p2 + p3));
        float dv   = bt * (vv - pred);

        // S_new = alpha*S_old + k (x) dv ;  o = q . S_new[:,vl]
        float o0 = 0.f, o1 = 0.f, o2 = 0.f, o3 = 0.f;
        #pragma unroll
        for (int kk = 0; kk < DH; kk += 4) {
            float4 k4 = *(const float4*)&sk[kk];
            float4 q4 = *(const float4*)&sq[kk];
            float s0 = fmaf(k4.x, dv, at * S[kk + 0]); S[kk + 0] = s0; o0 = fmaf(q4.x, s0, o0);
            float s1 = fmaf(k4.y, dv, at * S[kk + 1]); S[kk + 1] = s1; o1 = fmaf(q4.y, s1, o1);
            float s2 = fmaf(k4.z, dv, at * S[kk + 2]); S[kk + 2] = s2; o2 = fmaf(q4.z, s2, o2);
            float s3 = fmaf(k4.w, dv, at * S[kk + 3]); S[kk + 3] = s3; o3 = fmaf(q4.w, s3, o3);
        }
        attn[base + vl] = (o0 + o1) + (o2 + o3);
        __syncthreads();   // protect sk/sq before next iteration overwrites
    }

    float* so = state_out + (size_t)bh * DH * DH;
    #pragma unroll
    for (int kk = 0; kk < DH; ++kk) so[kk * DH + vl] = S[kk];
}

// ---------------- swiglu elementwise: hg = silu(hg) * hu -------------------
__global__ __launch_bounds__(256) void swiglu_kernel(float* __restrict__ hg,
                                                     const float* __restrict__ hu)
{
    size_t n = (size_t)BT * FF;
    for (size_t i = (size_t)blockIdx.x * blockDim.x + threadIdx.x; i < n;
         i += (size_t)gridDim.x * blockDim.x) {
        float g = hg[i];
        hg[i] = (g / (1.0f + expf(-g))) * hu[i];
    }
}

// ---------------- launch --------------------------------------------------
extern "C" void kernel_launch(void* const* d_in, const int* in_sizes, int n_in,
                              void* d_out, int out_size)
{
    const float* x     = (const float*)d_in[0];
    const float* state = (const float*)d_in[1];
    const float* wq    = (const float*)d_in[2];
    const float* wk    = (const float*)d_in[3];
    const float* wv    = (const float*)d_in[4];
    const float* wb    = (const float*)d_in[5];
    const float* wg    = (const float*)d_in[6];
    const float* wo    = (const float*)d_in[7];
    const float* wgate = (const float*)d_in[8];
    const float* wup   = (const float*)d_in[9];
    const float* wdown = (const float*)d_in[10];
    float* out = (float*)d_out;

    float *xn, *q, *k, *v, *beta, *alph, *attn, *x1, *xn2, *hg, *hu;
    cudaGetSymbolAddress((void**)&xn,   g_xn);
    cudaGetSymbolAddress((void**)&q,    g_q);
    cudaGetSymbolAddress((void**)&k,    g_k);
    cudaGetSymbolAddress((void**)&v,    g_v);
    cudaGetSymbolAddress((void**)&beta, g_beta);
    cudaGetSymbolAddress((void**)&alph, g_alph);
    cudaGetSymbolAddress((void**)&attn, g_attn);
    cudaGetSymbolAddress((void**)&x1,   g_x1);
    cudaGetSymbolAddress((void**)&xn2,  g_xn2);
    cudaGetSymbolAddress((void**)&hg,   g_hg);
    cudaGetSymbolAddress((void**)&hu,   g_hu);

    dim3 gD(DIM / 64, BT / 128);   // N=1024 GEMMs
    dim3 gF(FF / 64,  BT / 128);   // N=4096 GEMMs

    // 1) xn = rmsnorm(x)
    rmsnorm_kernel<<<BT, 256>>>(x, xn);
    // 2) projections
    gemm_kernel<<<gD, 256>>>(xn, wq, nullptr, q, BT, DIM, DIM);
    gemm_kernel<<<gD, 256>>>(xn, wk, nullptr, k, BT, DIM, DIM);
    gemm_kernel<<<gD, 256>>>(xn, wv, nullptr, v, BT, DIM, DIM);
    ba_kernel<<<BT, 256>>>(xn, wb, wg, beta, alph);
    // 3) silu + l2norm (q,k), silu (v)
    act_kernel<<<dim3(BT, NH), 128>>>(q, k, v);
    // 4) recurrent scan; writes attn (pre-wo) and final state into d_out tail
    scan_kernel<<<NB * NH, 128>>>(q, k, v, beta, alph, state,
                                  attn, out + (size_t)BT * DIM);
    // 5) x1 = x + attn @ wo
    gemm_kernel<<<gD, 256>>>(attn, wo, x, x1, BT, DIM, DIM);
    // 6) xn2 = rmsnorm(x1)
    rmsnorm_kernel<<<BT, 256>>>(x1, xn2);
    // 7) mlp
    gemm_kernel<<<gF, 256>>>(xn2, wgate, nullptr, hg, BT, FF, DIM);
    gemm_kernel<<<gF, 256>>>(xn2, wup,   nullptr, hu, BT, FF, DIM);
    swiglu_kernel<<<2048, 256>>>(hg, hu);
    // 8) out = x1 + hg @ wdown
    gemm_kernel<<<gD, 256>>>(hg, wdown, x1, out, BT, DIM, FF);
}

// round 3
// speedup vs baseline: 1.3963x; 1.3963x over previous
#include <cuda_runtime.h>
#include <math.h>
#include <stdint.h>

// Problem dims (fixed by the dataset)
#define BT  4096     // B*T tokens
#define DIM 1024     // model dim
#define FF  4096     // mlp dim
#define NH  8        // heads
#define DH  128      // head dim
#define NB  2        // batch
#define TT  2048     // seq len

// ---------------- scratch (device globals; no allocation allowed) ----------
__device__ float g_xn  [BT * DIM];
__device__ float g_q   [BT * DIM];
__device__ float g_k   [BT * DIM];
__device__ float g_v   [BT * DIM];
__device__ float g_beta[BT * NH];
__device__ float g_alph[BT * NH];
__device__ float g_attn[BT * DIM];
__device__ float g_x1  [BT * DIM];
__device__ float g_xn2 [BT * DIM];
__device__ float g_hg  [BT * FF];
__device__ float g_hu  [BT * FF];

// ---------------- rmsnorm: one block per row, 256 thr x 4 elems ------------
__global__ __launch_bounds__(256) void rmsnorm_kernel(const float* __restrict__ in,
                                                      float* __restrict__ out)
{
    int row = blockIdx.x;
    int i   = threadIdx.x * 4;
    const float* r = in + (size_t)row * DIM;
    float4 xv = *(const float4*)&r[i];
    float ss = xv.x*xv.x + xv.y*xv.y + xv.z*xv.z + xv.w*xv.w;

    #pragma unroll
    for (int o = 16; o > 0; o >>= 1) ss += __shfl_xor_sync(0xffffffffu, ss, o);
    __shared__ float sbuf[8];
    int w = threadIdx.x >> 5;
    if ((threadIdx.x & 31) == 0) sbuf[w] = ss;
    __syncthreads();
    float tot = sbuf[0]+sbuf[1]+sbuf[2]+sbuf[3]+sbuf[4]+sbuf[5]+sbuf[6]+sbuf[7];
    float scale = rsqrtf(tot * (1.0f / DIM) + 1e-6f);

    float4 ov;
    ov.x = xv.x*scale; ov.y = xv.y*scale; ov.z = xv.z*scale; ov.w = xv.w*scale;
    *(float4*)&out[(size_t)row * DIM + i] = ov;
}

// ---------------- TF32 tensor-core GEMM: C[M,N] = A[M,K] @ B[K,N] (+Res) ---
// BM=128, BN=128, BK=32; 256 threads = 8 warps in 2(m) x 4(n); warp tile 64x32.
// mma.sync.aligned.m16n8k8.row.col.f32.tf32.tf32.f32
// Requires M%128==0, N%128==0, K%32==0 (true for all calls here).

__device__ __forceinline__ uint32_t f2tf32(float f) {
    uint32_t u;
    asm("cvt.rna.tf32.f32 %0, %1;" : "=r"(u) : "f"(f));
    return u;
}

__global__ __launch_bounds__(256, 2) void gemm_tc_kernel(const float* __restrict__ A,
                                                         const float* __restrict__ B,
                                                         const float* __restrict__ Res,
                                                         float* __restrict__ C,
                                                         int M, int N, int K)
{
    const int BM = 128, BN = 128, BK = 32;
    const int AST = 36;    // As row stride (floats): banks 4g+t4 all distinct
    const int BST = 132;   // Bs row stride: banks 4*t4+g all distinct
    __shared__ __align__(16) uint32_t As[BM * AST];   // [m][k] tf32 bits
    __shared__ __align__(16) uint32_t Bs[BK * BST];   // [k][n] tf32 bits

    int tid  = threadIdx.x;
    int lane = tid & 31;
    int warp = tid >> 5;
    int g    = lane >> 2;     // group id 0..7
    int t4   = lane & 3;      // thread-in-group 0..3
    int wm   = warp & 1;      // 0..1 (m)
    int wn   = warp >> 1;     // 0..3 (n)
    int bm   = blockIdx.y * BM;
    int bn   = blockIdx.x * BN;

    // A tile gmem mapping: 4 passes of 32 rows x 32 cols
    int aRow0 = tid >> 3;          // 0..31
    int aCol  = (tid & 7) * 4;     // 0..28
    // B tile: idx = tid + 256*i; row = idx>>5, col=(idx&31)*4

    float acc[4][4][4];            // [mt][nt][frag]
    #pragma unroll
    for (int i = 0; i < 4; ++i)
        #pragma unroll
        for (int j = 0; j < 4; ++j)
            #pragma unroll
            for (int c = 0; c < 4; ++c) acc[i][j][c] = 0.f;

    for (int k0 = 0; k0 < K; k0 += BK) {
        // load A tile (128x32) -> As[m][k]
        #pragma unroll
        for (int i = 0; i < 4; ++i) {
            int r = aRow0 + 32 * i;
            float4 a = *(const float4*)&A[(size_t)(bm + r) * K + k0 + aCol];
            uint32_t* d = &As[r * AST + aCol];
            d[0] = f2tf32(a.x); d[1] = f2tf32(a.y);
            d[2] = f2tf32(a.z); d[3] = f2tf32(a.w);
        }
        // load B tile (32x128) -> Bs[k][n]
        #pragma unroll
        for (int i = 0; i < 4; ++i) {
            int idx = tid + 256 * i;
            int r = idx >> 5;
            int c = (idx & 31) * 4;
            float4 b = *(const float4*)&B[(size_t)(k0 + r) * N + bn + c];
            uint32_t* d = &Bs[r * BST + c];
            d[0] = f2tf32(b.x); d[1] = f2tf32(b.y);
            d[2] = f2tf32(b.z); d[3] = f2tf32(b.w);
        }
        __syncthreads();

        #pragma unroll
        for (int kc = 0; kc < BK; kc += 8) {
            // B fragments for this warp's 4 n-tiles
            uint32_t bf[4][2];
            #pragma unroll
            for (int nt = 0; nt < 4; ++nt) {
                int col = wn * 32 + nt * 8 + g;
                bf[nt][0] = Bs[(kc + t4)     * BST + col];
                bf[nt][1] = Bs[(kc + t4 + 4) * BST + col];
            }
            #pragma unroll
            for (int mt = 0; mt < 4; ++mt) {
                int row = wm * 64 + mt * 16 + g;
                uint32_t a0 = As[row       * AST + kc + t4];
                uint32_t a1 = As[(row + 8) * AST + kc + t4];
                uint32_t a2 = As[row       * AST + kc + t4 + 4];
                uint32_t a3 = As[(row + 8) * AST + kc + t4 + 4];
                #pragma unroll
                for (int nt = 0; nt < 4; ++nt) {
                    asm volatile(
                        "mma.sync.aligned.m16n8k8.row.col.f32.tf32.tf32.f32 "
                        "{%0,%1,%2,%3}, {%4,%5,%6,%7}, {%8,%9}, {%0,%1,%2,%3};"
                        : "+f"(acc[mt][nt][0]), "+f"(acc[mt][nt][1]),
                          "+f"(acc[mt][nt][2]), "+f"(acc[mt][nt][3])
                        : "r"(a0), "r"(a1), "r"(a2), "r"(a3),
                          "r"(bf[nt][0]), "r"(bf[nt][1]));
                }
            }
        }
        __syncthreads();
    }

    // epilogue: c0:(g, 2t4) c1:(g, 2t4+1) c2:(g+8, 2t4) c3:(g+8, 2t4+1)
    #pragma unroll
    for (int mt = 0; mt < 4; ++mt) {
        #pragma unroll
        for (int nt = 0; nt < 4; ++nt) {
            int row = bm + wm * 64 + mt * 16 + g;
            int col = bn + wn * 32 + nt * 8 + 2 * t4;
            size_t o0 = (size_t)row * N + col;
            size_t o1 = (size_t)(row + 8) * N + col;
            float2 u, l;
            u.x = acc[mt][nt][0]; u.y = acc[mt][nt][1];
            l.x = acc[mt][nt][2]; l.y = acc[mt][nt][3];
            if (Res) {
                float2 r0 = *(const float2*)&Res[o0];
                float2 r1 = *(const float2*)&Res[o1];
                u.x += r0.x; u.y += r0.y;
                l.x += r1.x; l.y += r1.y;
            }
            *(float2*)&C[o0] = u;
            *(float2*)&C[o1] = l;
        }
    }
}

// ---------------- beta/alpha: sigmoid(xn @ wb), sigmoid(xn @ wg) -----------
__global__ __launch_bounds__(256) void ba_kernel(const float* __restrict__ xn,
                                                 const float* __restrict__ wb,
                                                 const float* __restrict__ wg,
                                                 float* __restrict__ beta,
                                                 float* __restrict__ alph)
{
    __shared__ __align__(16) float xr[DIM];
    int tok = blockIdx.x;
    int t = threadIdx.x;
    *(float4*)&xr[t * 4] = *(const float4*)&xn[(size_t)tok * DIM + t * 4];
    __syncthreads();

    int w = t >> 5, lane = t & 31;
    float ab = 0.f, aa = 0.f;
    #pragma unroll 4
    for (int d = lane; d < DIM; d += 32) {
        float xv = xr[d];
        ab = fmaf(xv, wb[d * NH + w], ab);
        aa = fmaf(xv, wg[d * NH + w], aa);
    }
    #pragma unroll
    for (int o = 16; o > 0; o >>= 1) {
        ab += __shfl_xor_sync(0xffffffffu, ab, o);
        aa += __shfl_xor_sync(0xffffffffu, aa, o);
    }
    if (lane == 0) {
        beta[tok * NH + w] = 1.0f / (1.0f + expf(-ab));
        alph[tok * NH + w] = 1.0f / (1.0f + expf(-aa));
    }
}

// ---------------- activations: silu + per-head l2norm on q,k; silu on v ----
__global__ __launch_bounds__(128) void act_kernel(float* __restrict__ q,
                                                  float* __restrict__ k,
                                                  float* __restrict__ v)
{
    int tok = blockIdx.x, h = blockIdx.y, t = threadIdx.x;
    size_t idx = (size_t)tok * DIM + h * DH + t;
    float qv = q[idx], kv = k[idx], vv = v[idx];
    float qs = qv / (1.0f + expf(-qv));
    float ks = kv / (1.0f + expf(-kv));
    float vs = vv / (1.0f + expf(-vv));

    float a = qs * qs, b = ks * ks;
    #pragma unroll
    for (int o = 16; o > 0; o >>= 1) {
        a += __shfl_xor_sync(0xffffffffu, a, o);
        b += __shfl_xor_sync(0xffffffffu, b, o);
    }
    __shared__ float sq[4], sk[4];
    int w = t >> 5;
    if ((t & 31) == 0) { sq[w] = a; sk[w] = b; }
    __syncthreads();
    float qsum = sq[0] + sq[1] + sq[2] + sq[3];
    float ksum = sk[0] + sk[1] + sk[2] + sk[3];

    q[idx] = qs * rsqrtf(qsum + 1e-6f);
    k[idx] = ks * rsqrtf(ksum + 1e-6f);
    v[idx] = vs;
}

// ---------------- gated delta-rule scan: 16 blocks (b,h), S in registers ---
// Software-pipelined: t+1's global loads are issued before t's compute.
__global__ __launch_bounds__(128) void scan_kernel(const float* __restrict__ q,
                                                   const float* __restrict__ k,
                                                   const float* __restrict__ v,
                                                   const float* __restrict__ beta,
                                                   const float* __restrict__ alph,
                                                   const float* __restrict__ state_in,
                                                   float* __restrict__ attn,
                                                   float* __restrict__ state_out)
{
    int bh = blockIdx.x;         // b*NH + h
    int b  = bh >> 3;
    int h  = bh & 7;
    int vl = threadIdx.x;        // this thread owns state column v = vl

    float S[DH];                 // S[k][vl]
    const float* st = state_in + (size_t)bh * DH * DH;
    #pragma unroll
    for (int kk = 0; kk < DH; ++kk) S[kk] = st[kk * DH + vl];

    __shared__ __align__(16) float sk[DH];
    __shared__ __align__(16) float sq[DH];

    // prefetch t = 0
    size_t base0 = (size_t)(b * TT) * DIM + h * DH;
    float kv_c = k[base0 + vl];
    float qv_c = q[base0 + vl];
    float vv_c = v[base0 + vl];
    float bt_c = beta[(b * TT) * NH + h];
    float at_c = alph[(b * TT) * NH + h];

    for (int t = 0; t < TT; ++t) {
        int tok = b * TT + t;
        size_t base = (size_t)tok * DIM + h * DH;
        sk[vl] = kv_c;
        sq[vl] = qv_c;
        float vv = vv_c, bt = bt_c, at = at_c;
        __syncthreads();

        // prefetch t+1 (overlaps compute below)
        if (t + 1 < TT) {
            size_t nb_ = base + DIM;
            kv_c = k[nb_ + vl];
            qv_c = q[nb_ + vl];
            vv_c = v[nb_ + vl];
            bt_c = beta[(tok + 1) * NH + h];
            at_c = alph[(tok + 1) * NH + h];
        }

        // pred = alpha * (k . S_old[:,vl])
        float p0 = 0.f, p1 = 0.f, p2 = 0.f, p3 = 0.f;
        #pragma unroll
        for (int kk = 0; kk < DH; kk += 4) {
            float4 k4 = *(const float4*)&sk[kk];
            p0 = fmaf(k4.x, S[kk + 0], p0);
            p1 = fmaf(k4.y, S[kk + 1], p1);
            p2 = fmaf(k4.z, S[kk + 2], p2);
            p3 = fmaf(k4.w, S[kk + 3], p3);
        }
        float pred = at * ((p0 + p1) + (p2 + p3));
        float dv   = bt * (vv - pred);

        // S_new = alpha*S_old + k (x) dv ;  o = q . S_new[:,vl]
        float o0 = 0.f, o1 = 0.f, o2 = 0.f, o3 = 0.f;
        #pragma unroll
        for (int kk = 0; kk < DH; kk += 4) {
            float4 k4 = *(const float4*)&sk[kk];
            float4 q4 = *(const float4*)&sq[kk];
            float s0 = fmaf(k4.x, dv, at * S[kk + 0]); S[kk + 0] = s0; o0 = fmaf(q4.x, s0, o0);
            float s1 = fmaf(k4.y, dv, at * S[kk + 1]); S[kk + 1] = s1; o1 = fmaf(q4.y, s1, o1);
            float s2 = fmaf(k4.z, dv, at * S[kk + 2]); S[kk + 2] = s2; o2 = fmaf(q4.z, s2, o2);
            float s3 = fmaf(k4.w, dv, at * S[kk + 3]); S[kk + 3] = s3; o3 = fmaf(q4.w, s3, o3);
        }
        attn[base + vl] = (o0 + o1) + (o2 + o3);
        __syncthreads();   // protect sk/sq before next iteration overwrites
    }

    float* so = state_out + (size_t)bh * DH * DH;
    #pragma unroll
    for (int kk = 0; kk < DH; ++kk) so[kk * DH + vl] = S[kk];
}

// ---------------- swiglu elementwise: hg = silu(hg) * hu -------------------
__global__ __launch_bounds__(256) void swiglu_kernel(float* __restrict__ hg,
                                                     const float* __restrict__ hu)
{
    size_t n = (size_t)BT * FF;
    for (size_t i = (size_t)blockIdx.x * blockDim.x + threadIdx.x; i < n;
         i += (size_t)gridDim.x * blockDim.x) {
        float g = hg[i];
        hg[i] = (g / (1.0f + expf(-g))) * hu[i];
    }
}

// ---------------- launch --------------------------------------------------
extern "C" void kernel_launch(void* const* d_in, const int* in_sizes, int n_in,
                              void* d_out, int out_size)
{
    const float* x     = (const float*)d_in[0];
    const float* state = (const float*)d_in[1];
    const float* wq    = (const float*)d_in[2];
    const float* wk    = (const float*)d_in[3];
    const float* wv    = (const float*)d_in[4];
    const float* wb    = (const float*)d_in[5];
    const float* wg    = (const float*)d_in[6];
    const float* wo    = (const float*)d_in[7];
    const float* wgate = (const float*)d_in[8];
    const float* wup   = (const float*)d_in[9];
    const float* wdown = (const float*)d_in[10];
    float* out = (float*)d_out;

    float *xn, *q, *k, *v, *beta, *alph, *attn, *x1, *xn2, *hg, *hu;
    cudaGetSymbolAddress((void**)&xn,   g_xn);
    cudaGetSymbolAddress((void**)&q,    g_q);
    cudaGetSymbolAddress((void**)&k,    g_k);
    cudaGetSymbolAddress((void**)&v,    g_v);
    cudaGetSymbolAddress((void**)&beta, g_beta);
    cudaGetSymbolAddress((void**)&alph, g_alph);
    cudaGetSymbolAddress((void**)&attn, g_attn);
    cudaGetSymbolAddress((void**)&x1,   g_x1);
    cudaGetSymbolAddress((void**)&xn2,  g_xn2);
    cudaGetSymbolAddress((void**)&hg,   g_hg);
    cudaGetSymbolAddress((void**)&hu,   g_hu);

    dim3 gD(DIM / 128, BT / 128);   // N=1024 GEMMs: 8 x 32
    dim3 gF(FF / 128,  BT / 128);   // N=4096 GEMMs: 32 x 32

    // 1) xn = rmsnorm(x)
    rmsnorm_kernel<<<BT, 256>>>(x, xn);
    // 2) projections
    gemm_tc_kernel<<<gD, 256>>>(xn, wq, nullptr, q, BT, DIM, DIM);
    gemm_tc_kernel<<<gD, 256>>>(xn, wk, nullptr, k, BT, DIM, DIM);
    gemm_tc_kernel<<<gD, 256>>>(xn, wv, nullptr, v, BT, DIM, DIM);
    ba_kernel<<<BT, 256>>>(xn, wb, wg, beta, alph);
    // 3) silu + l2norm (q,k), silu (v)
    act_kernel<<<dim3(BT, NH), 128>>>(q, k, v);
    // 4) recurrent scan; writes attn (pre-wo) and final state into d_out tail
    scan_kernel<<<NB * NH, 128>>>(q, k, v, beta, alph, state,
                                  attn, out + (size_t)BT * DIM);
    // 5) x1 = x + attn @ wo
    gemm_tc_kernel<<<gD, 256>>>(attn, wo, x, x1, BT, DIM, DIM);
    // 6) xn2 = rmsnorm(x1)
    rmsnorm_kernel<<<BT, 256>>>(x1, xn2);
    // 7) mlp
    gemm_tc_kernel<<<gF, 256>>>(xn2, wgate, nullptr, hg, BT, FF, DIM);
    gemm_tc_kernel<<<gF, 256>>>(xn2, wup,   nullptr, hu, BT, FF, DIM);
    swiglu_kernel<<<2048, 256>>>(hg, hu);
    // 8) out = x1 + hg @ wdown
    gemm_tc_kernel<<<gD, 256>>>(hg, wdown, x1, out, BT, DIM, FF);
}

// round 4
// speedup vs baseline: 2.8732x; 2.0577x over previous
#include <cuda_runtime.h>
#include <math.h>
#include <stdint.h>

// Problem dims (fixed by the dataset)
#define BT  4096     // B*T tokens
#define DIM 1024     // model dim
#define FF  4096     // mlp dim
#define NH  8        // heads
#define DH  128      // head dim
#define NB  2        // batch
#define TT  2048     // seq len

// ---------------- scratch (device globals; no allocation allowed) ----------
__device__ float    g_xn  [BT * DIM];
__device__ float    g_q   [BT * DIM];
__device__ float    g_k   [BT * DIM];
__device__ float    g_v   [BT * DIM];
__device__ float    g_beta[BT * NH];
__device__ float    g_alph[BT * NH];
__device__ float    g_x1  [BT * DIM];
__device__ float    g_xn2 [BT * DIM];
__device__ float    g_hg  [BT * FF];
__device__ float    g_hu  [BT * FF];
// tf32-bit copies (GEMM operands)
__device__ uint32_t g_xn_t  [BT * DIM];
__device__ uint32_t g_xn2_t [BT * DIM];
__device__ uint32_t g_attn_t[BT * DIM];
__device__ uint32_t g_hg_t  [BT * FF];
__device__ uint32_t g_wq_t  [DIM * DIM];
__device__ uint32_t g_wk_t  [DIM * DIM];
__device__ uint32_t g_wv_t  [DIM * DIM];
__device__ uint32_t g_wo_t  [DIM * DIM];
__device__ uint32_t g_wga_t [DIM * FF];
__device__ uint32_t g_wup_t [DIM * FF];
__device__ uint32_t g_wdn_t [FF * DIM];

__device__ __forceinline__ uint32_t f2tf32(float f) {
    uint32_t u;
    asm("cvt.rna.tf32.f32 %0, %1;" : "=r"(u) : "f"(f));
    return u;
}

// ---------------- tf32 converter (weights) ---------------------------------
__global__ __launch_bounds__(256) void conv_tf32_kernel(const float* __restrict__ in,
                                                        uint32_t* __restrict__ out, int n)
{
    int i = (blockIdx.x * blockDim.x + threadIdx.x) * 4;
    if (i < n) {
        float4 v = *(const float4*)&in[i];
        uint4 o;
        o.x = f2tf32(v.x); o.y = f2tf32(v.y); o.z = f2tf32(v.z); o.w = f2tf32(v.w);
        *(uint4*)&out[i] = o;
    }
}

// ---------------- rmsnorm: fp32 out + tf32 out -----------------------------
__global__ __launch_bounds__(256) void rmsnorm_kernel(const float* __restrict__ in,
                                                      float* __restrict__ out,
                                                      uint32_t* __restrict__ out_t)
{
    int row = blockIdx.x;
    int i   = threadIdx.x * 4;
    const float* r = in + (size_t)row * DIM;
    float4 xv = *(const float4*)&r[i];
    float ss = xv.x*xv.x + xv.y*xv.y + xv.z*xv.z + xv.w*xv.w;

    #pragma unroll
    for (int o = 16; o > 0; o >>= 1) ss += __shfl_xor_sync(0xffffffffu, ss, o);
    __shared__ float sbuf[8];
    int w = threadIdx.x >> 5;
    if ((threadIdx.x & 31) == 0) sbuf[w] = ss;
    __syncthreads();
    float tot = sbuf[0]+sbuf[1]+sbuf[2]+sbuf[3]+sbuf[4]+sbuf[5]+sbuf[6]+sbuf[7];
    float scale = rsqrtf(tot * (1.0f / DIM) + 1e-6f);

    float4 ov;
    ov.x = xv.x*scale; ov.y = xv.y*scale; ov.z = xv.z*scale; ov.w = xv.w*scale;
    size_t off = (size_t)row * DIM + i;
    *(float4*)&out[off] = ov;
    uint4 ot;
    ot.x = f2tf32(ov.x); ot.y = f2tf32(ov.y); ot.z = f2tf32(ov.z); ot.w = f2tf32(ov.w);
    *(uint4*)&out_t[off] = ot;
}

// ---------------- TF32 tensor-core GEMM, cp.async double-buffered ----------
// A,B hold pre-converted tf32 bits. C[M,N] = A[M,K] @ B[K,N] (+Res), fp32 out.
// BM=128, BN=128, BK=32; 256 threads = 8 warps in 2(m) x 4(n); warp tile 64x32.

#define AST 36    // As row stride (uints): 144B, 16B-aligned, conflict-free frags
#define BST 132   // Bs row stride: 528B, 16B-aligned
#define A_STAGE (128 * AST)   // 4608
#define B_STAGE (32 * BST)    // 4224
#define GEMM_SMEM ((2 * A_STAGE + 2 * B_STAGE) * 4)   // 70656 bytes

__device__ __forceinline__ void cp16(uint32_t smem_dst, const void* gsrc) {
    asm volatile("cp.async.cg.shared.global [%0], [%1], 16;" :: "r"(smem_dst), "l"(gsrc));
}

__global__ __launch_bounds__(256, 2) void gemm_tc_kernel(const uint32_t* __restrict__ A,
                                                         const uint32_t* __restrict__ B,
                                                         const float* __restrict__ Res,
                                                         float* __restrict__ C,
                                                         int M, int N, int K)
{
    extern __shared__ __align__(16) uint32_t sm[];
    uint32_t* As = sm;                 // [2][A_STAGE]
    uint32_t* Bs = sm + 2 * A_STAGE;   // [2][B_STAGE]

    int tid  = threadIdx.x;
    int lane = tid & 31;
    int warp = tid >> 5;
    int g    = lane >> 2;     // 0..7
    int t4   = lane & 3;      // 0..3
    int wm   = warp & 1;
    int wn   = warp >> 1;
    int bm   = blockIdx.y * 128;
    int bn   = blockIdx.x * 128;

    int aRow0 = tid >> 3;          // 0..31
    int aCol  = (tid & 7) * 4;     // 0..28

    float acc[4][4][4];
    #pragma unroll
    for (int i = 0; i < 4; ++i)
        #pragma unroll
        for (int j = 0; j < 4; ++j)
            #pragma unroll
            for (int c = 0; c < 4; ++c) acc[i][j][c] = 0.f;

    int nIter = K >> 5;

    // stage copy helper (macro-ish via lambda)
    auto copy_stage = [&](int it, int stg) {
        int k0 = it << 5;
        #pragma unroll
        for (int i = 0; i < 4; ++i) {
            int r = aRow0 + 32 * i;
            uint32_t dst = (uint32_t)__cvta_generic_to_shared(&As[stg * A_STAGE + r * AST + aCol]);
            cp16(dst, &A[(size_t)(bm + r) * K + k0 + aCol]);
        }
        #pragma unroll
        for (int i = 0; i < 4; ++i) {
            int idx = tid + 256 * i;
            int r = idx >> 5;
            int c = (idx & 31) * 4;
            uint32_t dst = (uint32_t)__cvta_generic_to_shared(&Bs[stg * B_STAGE + r * BST + c]);
            cp16(dst, &B[(size_t)(k0 + r) * N + bn + c]);
        }
        asm volatile("cp.async.commit_group;");
    };

    copy_stage(0, 0);

    for (int it = 0; it < nIter; ++it) {
        if (it + 1 < nIter) {
            copy_stage(it + 1, (it + 1) & 1);
            asm volatile("cp.async.wait_group 1;");
        } else {
            asm volatile("cp.async.wait_group 0;");
        }
        __syncthreads();

        const uint32_t* Ac = As + (it & 1) * A_STAGE;
        const uint32_t* Bc = Bs + (it & 1) * B_STAGE;

        #pragma unroll
        for (int kc = 0; kc < 32; kc += 8) {
            uint32_t bf[4][2];
            #pragma unroll
            for (int nt = 0; nt < 4; ++nt) {
                int col = wn * 32 + nt * 8 + g;
                bf[nt][0] = Bc[(kc + t4)     * BST + col];
                bf[nt][1] = Bc[(kc + t4 + 4) * BST + col];
            }
            #pragma unroll
            for (int mt = 0; mt < 4; ++mt) {
                int row = wm * 64 + mt * 16 + g;
                uint32_t a0 = Ac[row       * AST + kc + t4];
                uint32_t a1 = Ac[(row + 8) * AST + kc + t4];
                uint32_t a2 = Ac[row       * AST + kc + t4 + 4];
                uint32_t a3 = Ac[(row + 8) * AST + kc + t4 + 4];
                #pragma unroll
                for (int nt = 0; nt < 4; ++nt) {
                    asm volatile(
                        "mma.sync.aligned.m16n8k8.row.col.f32.tf32.tf32.f32 "
                        "{%0,%1,%2,%3}, {%4,%5,%6,%7}, {%8,%9}, {%0,%1,%2,%3};"
                        : "+f"(acc[mt][nt][0]), "+f"(acc[mt][nt][1]),
                          "+f"(acc[mt][nt][2]), "+f"(acc[mt][nt][3])
                        : "r"(a0), "r"(a1), "r"(a2), "r"(a3),
                          "r"(bf[nt][0]), "r"(bf[nt][1]));
                }
            }
        }
        __syncthreads();
    }

    #pragma unroll
    for (int mt = 0; mt < 4; ++mt) {
        #pragma unroll
        for (int nt = 0; nt < 4; ++nt) {
            int row = bm + wm * 64 + mt * 16 + g;
            int col = bn + wn * 32 + nt * 8 + 2 * t4;
            size_t o0 = (size_t)row * N + col;
            size_t o1 = (size_t)(row + 8) * N + col;
            float2 u, l;
            u.x = acc[mt][nt][0]; u.y = acc[mt][nt][1];
            l.x = acc[mt][nt][2]; l.y = acc[mt][nt][3];
            if (Res) {
                float2 r0 = *(const float2*)&Res[o0];
                float2 r1 = *(const float2*)&Res[o1];
                u.x += r0.x; u.y += r0.y;
                l.x += r1.x; l.y += r1.y;
            }
            *(float2*)&C[o0] = u;
            *(float2*)&C[o1] = l;
        }
    }
}

// ---------------- beta/alpha: sigmoid(xn @ wb), sigmoid(xn @ wg) -----------
__global__ __launch_bounds__(256) void ba_kernel(const float* __restrict__ xn,
                                                 const float* __restrict__ wb,
                                                 const float* __restrict__ wg,
                                                 float* __restrict__ beta,
                                                 float* __restrict__ alph)
{
    __shared__ __align__(16) float xr[DIM];
    int tok = blockIdx.x;
    int t = threadIdx.x;
    *(float4*)&xr[t * 4] = *(const float4*)&xn[(size_t)tok * DIM + t * 4];
    __syncthreads();

    int w = t >> 5, lane = t & 31;
    float ab = 0.f, aa = 0.f;
    #pragma unroll 4
    for (int d = lane; d < DIM; d += 32) {
        float xv = xr[d];
        ab = fmaf(xv, wb[d * NH + w], ab);
        aa = fmaf(xv, wg[d * NH + w], aa);
    }
    #pragma unroll
    for (int o = 16; o > 0; o >>= 1) {
        ab += __shfl_xor_sync(0xffffffffu, ab, o);
        aa += __shfl_xor_sync(0xffffffffu, aa, o);
    }
    if (lane == 0) {
        beta[tok * NH + w] = 1.0f / (1.0f + expf(-ab));
        alph[tok * NH + w] = 1.0f / (1.0f + expf(-aa));
    }
}

// ---------------- activations: silu + per-head l2norm on q,k; silu on v ----
__global__ __launch_bounds__(128) void act_kernel(float* __restrict__ q,
                                                  float* __restrict__ k,
                                                  float* __restrict__ v)
{
    int tok = blockIdx.x, h = blockIdx.y, t = threadIdx.x;
    size_t idx = (size_t)tok * DIM + h * DH + t;
    float qv = q[idx], kv = k[idx], vv = v[idx];
    float qs = qv / (1.0f + expf(-qv));
    float ks = kv / (1.0f + expf(-kv));
    float vs = vv / (1.0f + expf(-vv));

    float a = qs * qs, b = ks * ks;
    #pragma unroll
    for (int o = 16; o > 0; o >>= 1) {
        a += __shfl_xor_sync(0xffffffffu, a, o);
        b += __shfl_xor_sync(0xffffffffu, b, o);
    }
    __shared__ float sq[4], sk[4];
    int w = t >> 5;
    if ((t & 31) == 0) { sq[w] = a; sk[w] = b; }
    __syncthreads();
    float qsum = sq[0] + sq[1] + sq[2] + sq[3];
    float ksum = sk[0] + sk[1] + sk[2] + sk[3];

    q[idx] = qs * rsqrtf(qsum + 1e-6f);
    k[idx] = ks * rsqrtf(ksum + 1e-6f);
    v[idx] = vs;
}

// ---------------- gated delta-rule scan, 4-way k-split ---------------------
// 64 blocks = (bh 0..15) x (column-group 0..3). Block: 128 threads; thread
// (warp w, lane l) owns column colL = w*8 + (l&7) of its group and k-rows
// [seg*32, seg*32+32) where seg = l>>3. Partial dots reduced by shfl over
// bits 3,4 of the lane. One __syncthreads per step (double-buffered k/q).
__global__ __launch_bounds__(128) void scan_kernel(const float* __restrict__ q,
                                                   const float* __restrict__ k,
                                                   const float* __restrict__ v,
                                                   const float* __restrict__ beta,
                                                   const float* __restrict__ alph,
                                                   const float* __restrict__ state_in,
                                                   uint32_t* __restrict__ attn_t,
                                                   float* __restrict__ state_out)
{
    int blk = blockIdx.x;
    int bh  = blk >> 2;
    int grp = blk & 3;
    int b = bh >> 3, h = bh & 7;
    int tid = threadIdx.x;
    int w = tid >> 5, lane = tid & 31;
    int colL  = w * 8 + (lane & 7);   // 0..31
    int seg   = lane >> 3;            // 0..3
    int vcol  = grp * 32 + colL;      // global state column
    int rbase = seg * 32;             // this thread's k-row range

    float S[32];
    const float* st = state_in + (size_t)bh * DH * DH;
    #pragma unroll
    for (int i = 0; i < 32; ++i) S[i] = st[(rbase + i) * DH + vcol];

    __shared__ __align__(16) float sk[2][DH];
    __shared__ __align__(16) float sq[2][DH];

    size_t base0 = (size_t)(b * TT) * DIM + h * DH;
    float k_c = k[base0 + tid];
    float q_c = q[base0 + tid];
    float v_c = v[base0 + vcol];
    float b_c = beta[(b * TT) * NH + h];
    float a_c = alph[(b * TT) * NH + h];

    for (int t = 0; t < TT; ++t) {
        int tok = b * TT + t;
        size_t base = (size_t)tok * DIM + h * DH;
        int buf = t & 1;
        sk[buf][tid] = k_c;
        sq[buf][tid] = q_c;
        float vv = v_c, bt = b_c, at = a_c;
        __syncthreads();

        if (t + 1 < TT) {                       // prefetch next step
            size_t nb = base + DIM;
            k_c = k[nb + tid];
            q_c = q[nb + tid];
            v_c = v[nb + vcol];
            b_c = beta[(tok + 1) * NH + h];
            a_c = alph[(tok + 1) * NH + h];
        }

        // partial pred over this thread's 32 k-rows
        float p0 = 0.f, p1 = 0.f, p2 = 0.f, p3 = 0.f;
        #pragma unroll
        for (int i = 0; i < 32; i += 4) {
            float4 k4 = *(const float4*)&sk[buf][rbase + i];
            p0 = fmaf(k4.x, S[i + 0], p0);
            p1 = fmaf(k4.y, S[i + 1], p1);
            p2 = fmaf(k4.z, S[i + 2], p2);
            p3 = fmaf(k4.w, S[i + 3], p3);
        }
        float pred = (p0 + p1) + (p2 + p3);
        pred += __shfl_xor_sync(0xffffffffu, pred, 8);
        pred += __shfl_xor_sync(0xffffffffu, pred, 16);
        float dv = bt * (vv - at * pred);

        // update + partial output
        float o0 = 0.f, o1 = 0.f, o2 = 0.f, o3 = 0.f;
        #pragma unroll
        for (int i = 0; i < 32; i += 4) {
            float4 k4 = *(const float4*)&sk[buf][rbase + i];
            float4 q4 = *(const float4*)&sq[buf][rbase + i];
            float s0 = fmaf(k4.x, dv, at * S[i + 0]); S[i + 0] = s0; o0 = fmaf(q4.x, s0, o0);
            float s1 = fmaf(k4.y, dv, at * S[i + 1]); S[i + 1] = s1; o1 = fmaf(q4.y, s1, o1);
            float s2 = fmaf(k4.z, dv, at * S[i + 2]); S[i + 2] = s2; o2 = fmaf(q4.z, s2, o2);
            float s3 = fmaf(k4.w, dv, at * S[i + 3]); S[i + 3] = s3; o3 = fmaf(q4.w, s3, o3);
        }
        float o = (o0 + o1) + (o2 + o3);
        o += __shfl_xor_sync(0xffffffffu, o, 8);
        o += __shfl_xor_sync(0xffffffffu, o, 16);
        if (seg == 0) attn_t[base + vcol] = f2tf32(o);
    }

    float* so = state_out + (size_t)bh * DH * DH;
    #pragma unroll
    for (int i = 0; i < 32; ++i) so[(rbase + i) * DH + vcol] = S[i];
}

// ---------------- swiglu: hg_t = tf32(silu(hg) * hu) -----------------------
__global__ __launch_bounds__(256) void swiglu_kernel(const float* __restrict__ hg,
                                                     const float* __restrict__ hu,
                                                     uint32_t* __restrict__ hg_t)
{
    size_t n = (size_t)BT * FF;
    for (size_t i = (size_t)blockIdx.x * blockDim.x + threadIdx.x; i < n;
         i += (size_t)gridDim.x * blockDim.x) {
        float g = hg[i];
        hg_t[i] = f2tf32((g / (1.0f + expf(-g))) * hu[i]);
    }
}

// ---------------- launch --------------------------------------------------
extern "C" void kernel_launch(void* const* d_in, const int* in_sizes, int n_in,
                              void* d_out, int out_size)
{
    const float* x     = (const float*)d_in[0];
    const float* state = (const float*)d_in[1];
    const float* wq    = (const float*)d_in[2];
    const float* wk    = (const float*)d_in[3];
    const float* wv    = (const float*)d_in[4];
    const float* wb    = (const float*)d_in[5];
    const float* wg    = (const float*)d_in[6];
    const float* wo    = (const float*)d_in[7];
    const float* wgate = (const float*)d_in[8];
    const float* wup   = (const float*)d_in[9];
    const float* wdown = (const float*)d_in[10];
    float* out = (float*)d_out;

    float *xn, *q, *k, *v, *beta, *alph, *x1, *xn2, *hg, *hu;
    uint32_t *xn_t, *xn2_t, *attn_t, *hg_t;
    uint32_t *wq_t, *wk_t, *wv_t, *wo_t, *wga_t, *wup_t, *wdn_t;
    cudaGetSymbolAddress((void**)&xn,    g_xn);
    cudaGetSymbolAddress((void**)&q,     g_q);
    cudaGetSymbolAddress((void**)&k,     g_k);
    cudaGetSymbolAddress((void**)&v,     g_v);
    cudaGetSymbolAddress((void**)&beta,  g_beta);
    cudaGetSymbolAddress((void**)&alph,  g_alph);
    cudaGetSymbolAddress((void**)&x1,    g_x1);
    cudaGetSymbolAddress((void**)&xn2,   g_xn2);
    cudaGetSymbolAddress((void**)&hg,    g_hg);
    cudaGetSymbolAddress((void**)&hu,    g_hu);
    cudaGetSymbolAddress((void**)&xn_t,  g_xn_t);
    cudaGetSymbolAddress((void**)&xn2_t, g_xn2_t);
    cudaGetSymbolAddress((void**)&attn_t,g_attn_t);
    cudaGetSymbolAddress((void**)&hg_t,  g_hg_t);
    cudaGetSymbolAddress((void**)&wq_t,  g_wq_t);
    cudaGetSymbolAddress((void**)&wk_t,  g_wk_t);
    cudaGetSymbolAddress((void**)&wv_t,  g_wv_t);
    cudaGetSymbolAddress((void**)&wo_t,  g_wo_t);
    cudaGetSymbolAddress((void**)&wga_t, g_wga_t);
    cudaGetSymbolAddress((void**)&wup_t, g_wup_t);
    cudaGetSymbolAddress((void**)&wdn_t, g_wdn_t);

    cudaFuncSetAttribute(gemm_tc_kernel,
                         cudaFuncAttributeMaxDynamicSharedMemorySize, GEMM_SMEM);

    dim3 gD(DIM / 128, BT / 128);   // N=1024 GEMMs: 8 x 32
    dim3 gF(FF / 128,  BT / 128);   // N=4096 GEMMs: 32 x 32
    const int CB = 256 * 4;         // elems per converter block

    // 0) weight -> tf32 conversions (independent of data path)
    conv_tf32_kernel<<<DIM*DIM/CB, 256>>>(wq,    wq_t,  DIM*DIM);
    conv_tf32_kernel<<<DIM*DIM/CB, 256>>>(wk,    wk_t,  DIM*DIM);
    conv_tf32_kernel<<<DIM*DIM/CB, 256>>>(wv,    wv_t,  DIM*DIM);
    conv_tf32_kernel<<<DIM*DIM/CB, 256>>>(wo,    wo_t,  DIM*DIM);
    conv_tf32_kernel<<<DIM*FF/CB,  256>>>(wgate, wga_t, DIM*FF);
    conv_tf32_kernel<<<DIM*FF/CB,  256>>>(wup,   wup_t, DIM*FF);
    conv_tf32_kernel<<<FF*DIM/CB,  256>>>(wdown, wdn_t, FF*DIM);

    // 1) xn = rmsnorm(x)  (fp32 + tf32)
    rmsnorm_kernel<<<BT, 256>>>(x, xn, xn_t);
    // 2) projections
    gemm_tc_kernel<<<gD, 256, GEMM_SMEM>>>(xn_t, wq_t, nullptr, q, BT, DIM, DIM);
    gemm_tc_kernel<<<gD, 256, GEMM_SMEM>>>(xn_t, wk_t, nullptr, k, BT, DIM, DIM);
    gemm_tc_kernel<<<gD, 256, GEMM_SMEM>>>(xn_t, wv_t, nullptr, v, BT, DIM, DIM);
    ba_kernel<<<BT, 256>>>(xn, wb, wg, beta, alph);
    // 3) silu + l2norm (q,k), silu (v)
    act_kernel<<<dim3(BT, NH), 128>>>(q, k, v);
    // 4) recurrent scan; writes attn (tf32) and final state into d_out tail
    scan_kernel<<<NB * NH * 4, 128>>>(q, k, v, beta, alph, state,
                                      attn_t, out + (size_t)BT * DIM);
    // 5) x1 = x + attn @ wo
    gemm_tc_kernel<<<gD, 256, GEMM_SMEM>>>(attn_t, wo_t, x, x1, BT, DIM, DIM);
    // 6) xn2 = rmsnorm(x1)
    rmsnorm_kernel<<<BT, 256>>>(x1, xn2, xn2_t);
    // 7) mlp
    gemm_tc_kernel<<<gF, 256, GEMM_SMEM>>>(xn2_t, wga_t, nullptr, hg, BT, FF, DIM);
    gemm_tc_kernel<<<gF, 256, GEMM_SMEM>>>(xn2_t, wup_t, nullptr, hu, BT, FF, DIM);
    swiglu_kernel<<<2048, 256>>>(hg, hu, hg_t);
    // 8) out = x1 + hg @ wdown
    gemm_tc_kernel<<<gD, 256, GEMM_SMEM>>>(hg_t, wdn_t, x1, out, BT, DIM, FF);
}

// round 6
// speedup vs baseline: 3.8532x; 1.3411x over previous
#include <cuda_runtime.h>
#include <cuda_fp16.h>
#include <math.h>
#include <stdint.h>

// Problem dims (fixed by the dataset)
#define BT  4096     // B*T tokens
#define DIM 1024     // model dim
#define FF  4096     // mlp dim
#define NH  8        // heads
#define DH  128      // head dim
#define NB  2        // batch
#define TT  2048     // seq len

// ---------------- scratch (device globals; no allocation allowed) ----------
__device__ float  g_xn  [BT * DIM];
__device__ float  g_q   [BT * DIM];
__device__ float  g_k   [BT * DIM];
__device__ float  g_v   [BT * DIM];
__device__ float  g_beta[BT * NH];
__device__ float  g_alph[BT * NH];
__device__ float  g_x1  [BT * DIM];
__device__ float  g_xn2 [BT * DIM];
__device__ float  g_hu  [BT * FF];
__device__ float  g_hg  [BT * FF];
// half copies (GEMM operands); weights stored TRANSPOSED [N][K]
__device__ __half g_xn_h  [BT * DIM];
__device__ __half g_xn2_h [BT * DIM];
__device__ __half g_attn_h[BT * DIM];
__device__ __half g_hg_h  [BT * FF];
__device__ __half g_wq_h  [DIM * DIM];
__device__ __half g_wk_h  [DIM * DIM];
__device__ __half g_wv_h  [DIM * DIM];
__device__ __half g_wo_h  [DIM * DIM];
__device__ __half g_wga_h [DIM * FF];
__device__ __half g_wup_h [DIM * FF];
__device__ __half g_wdn_h [FF * DIM];

// ---------------- transpose + fp32->half: in[K][N] -> out[N][K] ------------
__global__ __launch_bounds__(256) void conv_tr_kernel(const float* __restrict__ in,
                                                      __half* __restrict__ out,
                                                      int K, int N)
{
    __shared__ float s[32][33];
    int bx = blockIdx.x * 32;  // n base
    int by = blockIdx.y * 32;  // k base
    int tx = threadIdx.x, ty = threadIdx.y;
    #pragma unroll
    for (int j = 0; j < 4; ++j)
        s[ty + 8 * j][tx] = in[(size_t)(by + ty + 8 * j) * N + bx + tx];
    __syncthreads();
    #pragma unroll
    for (int j = 0; j < 4; ++j)
        out[(size_t)(bx + ty + 8 * j) * K + by + tx] = __float2half_rn(s[tx][ty + 8 * j]);
}

// ---------------- rmsnorm: fp32 out + half out -----------------------------
__global__ __launch_bounds__(256) void rmsnorm_kernel(const float* __restrict__ in,
                                                      float* __restrict__ out,
                                                      __half* __restrict__ out_h)
{
    int row = blockIdx.x;
    int i   = threadIdx.x * 4;
    const float* r = in + (size_t)row * DIM;
    float4 xv = *(const float4*)&r[i];
    float ss = xv.x*xv.x + xv.y*xv.y + xv.z*xv.z + xv.w*xv.w;

    #pragma unroll
    for (int o = 16; o > 0; o >>= 1) ss += __shfl_xor_sync(0xffffffffu, ss, o);
    __shared__ float sbuf[8];
    int w = threadIdx.x >> 5;
    if ((threadIdx.x & 31) == 0) sbuf[w] = ss;
    __syncthreads();
    float tot = sbuf[0]+sbuf[1]+sbuf[2]+sbuf[3]+sbuf[4]+sbuf[5]+sbuf[6]+sbuf[7];
    float scale = rsqrtf(tot * (1.0f / DIM) + 1e-6f);

    float4 ov;
    ov.x = xv.x*scale; ov.y = xv.y*scale; ov.z = xv.z*scale; ov.w = xv.w*scale;
    size_t off = (size_t)row * DIM + i;
    *(float4*)&out[off] = ov;
    __half2 h0 = __floats2half2_rn(ov.x, ov.y);
    __half2 h1 = __floats2half2_rn(ov.z, ov.w);
    *(__half2*)&out_h[off]     = h0;
    *(__half2*)&out_h[off + 2] = h1;
}

// ---------------- FP16 tensor-core GEMM, cp.async double-buffered ----------
// C[M,N] = A[M,K] @ Bt[N,K]^T (+Res), fp32 accumulate/out.
// BM=128, BN=128, BK=64; 256 threads = 8 warps 2(m)x4(n); warp tile 64x32.
// mma.sync.aligned.m16n8k16.row.col.f32.f16.f16.f32

#define AST_H 72                    // smem row stride in halves (144B)
#define A_STG (128 * AST_H)         // 9216 halves per stage
#define GEMM_SMEM (4 * A_STG * 2)   // 73728 bytes (2 stages A + 2 stages B)

__device__ __forceinline__ void cp16(uint32_t smem_dst, const void* gsrc) {
    asm volatile("cp.async.cg.shared.global [%0], [%1], 16;" :: "r"(smem_dst), "l"(gsrc));
}

__global__ __launch_bounds__(256, 2) void gemm_h_kernel(const __half* __restrict__ A,
                                                        const __half* __restrict__ Bt,
                                                        const float* __restrict__ Res,
                                                        float* __restrict__ C,
                                                        int M, int N, int K)
{
    extern __shared__ __align__(16) __half sm[];
    __half* As = sm;                  // [2][A_STG]
    __half* Bs = sm + 2 * A_STG;      // [2][A_STG]

    int tid  = threadIdx.x;
    int lane = tid & 31;
    int warp = tid >> 5;
    int g    = lane >> 2;     // 0..7
    int t4   = lane & 3;      // 0..3
    int wm   = warp & 1;
    int wn   = warp >> 1;
    int bm   = blockIdx.y * 128;
    int bn   = blockIdx.x * 128;

    int cRow  = tid >> 1;            // 0..127
    int cBase = (tid & 1) * 4;       // 16B-chunk base (0 or 4)

    float acc[4][4][4];
    #pragma unroll
    for (int i = 0; i < 4; ++i)
        #pragma unroll
        for (int j = 0; j < 4; ++j)
            #pragma unroll
            for (int c = 0; c < 4; ++c) acc[i][j][c] = 0.f;

    int nIter = K >> 6;

    auto copy_stage = [&](int it, int stg) {
        int k0 = it << 6;
        #pragma unroll
        for (int i = 0; i < 4; ++i) {
            int c = cBase + i;       // 16B chunk = 8 halves
            uint32_t da = (uint32_t)__cvta_generic_to_shared(&As[stg * A_STG + cRow * AST_H + c * 8]);
            cp16(da, &A[(size_t)(bm + cRow) * K + k0 + c * 8]);
            uint32_t db = (uint32_t)__cvta_generic_to_shared(&Bs[stg * A_STG + cRow * AST_H + c * 8]);
            cp16(db, &Bt[(size_t)(bn + cRow) * K + k0 + c * 8]);
        }
        asm volatile("cp.async.commit_group;");
    };

    copy_stage(0, 0);

    for (int it = 0; it < nIter; ++it) {
        if (it + 1 < nIter) {
            copy_stage(it + 1, (it + 1) & 1);
            asm volatile("cp.async.wait_group 1;");
        } else {
            asm volatile("cp.async.wait_group 0;");
        }
        __syncthreads();

        const __half* Ac = As + (it & 1) * A_STG;
        const __half* Bc = Bs + (it & 1) * A_STG;

        #pragma unroll
        for (int kc = 0; kc < 64; kc += 16) {
            uint32_t bf[4][2];
            #pragma unroll
            for (int nt = 0; nt < 4; ++nt) {
                const __half* bp = &Bc[(wn * 32 + nt * 8 + g) * AST_H + kc + 2 * t4];
                bf[nt][0] = *(const uint32_t*)bp;
                bf[nt][1] = *(const uint32_t*)(bp + 8);
            }
            #pragma unroll
            for (int mt = 0; mt < 4; ++mt) {
                int row = wm * 64 + mt * 16 + g;
                const __half* ap0 = &Ac[row       * AST_H + kc + 2 * t4];
                const __half* ap1 = &Ac[(row + 8) * AST_H + kc + 2 * t4];
                uint32_t a0 = *(const uint32_t*)ap0;
                uint32_t a1 = *(const uint32_t*)ap1;
                uint32_t a2 = *(const uint32_t*)(ap0 + 8);
                uint32_t a3 = *(const uint32_t*)(ap1 + 8);
                #pragma unroll
                for (int nt = 0; nt < 4; ++nt) {
                    asm volatile(
                        "mma.sync.aligned.m16n8k16.row.col.f32.f16.f16.f32 "
                        "{%0,%1,%2,%3}, {%4,%5,%6,%7}, {%8,%9}, {%0,%1,%2,%3};"
                        : "+f"(acc[mt][nt][0]), "+f"(acc[mt][nt][1]),
                          "+f"(acc[mt][nt][2]), "+f"(acc[mt][nt][3])
                        : "r"(a0), "r"(a1), "r"(a2), "r"(a3),
                          "r"(bf[nt][0]), "r"(bf[nt][1]));
                }
            }
        }
        __syncthreads();
    }

    #pragma unroll
    for (int mt = 0; mt < 4; ++mt) {
        #pragma unroll
        for (int nt = 0; nt < 4; ++nt) {
            int row = bm + wm * 64 + mt * 16 + g;
            int col = bn + wn * 32 + nt * 8 + 2 * t4;
            size_t o0 = (size_t)row * N + col;
            size_t o1 = (size_t)(row + 8) * N + col;
            float2 u, l;
            u.x = acc[mt][nt][0]; u.y = acc[mt][nt][1];
            l.x = acc[mt][nt][2]; l.y = acc[mt][nt][3];
            if (Res) {
                float2 r0 = *(const float2*)&Res[o0];
                float2 r1 = *(const float2*)&Res[o1];
                u.x += r0.x; u.y += r0.y;
                l.x += r1.x; l.y += r1.y;
            }
            *(float2*)&C[o0] = u;
            *(float2*)&C[o1] = l;
        }
    }
}

// ---------------- beta/alpha: sigmoid(xn @ wb), sigmoid(xn @ wg) -----------
__global__ __launch_bounds__(256) void ba_kernel(const float* __restrict__ xn,
                                                 const float* __restrict__ wb,
                                                 const float* __restrict__ wg,
                                                 float* __restrict__ beta,
                                                 float* __restrict__ alph)
{
    __shared__ __align__(16) float xr[DIM];
    int tok = blockIdx.x;
    int t = threadIdx.x;
    *(float4*)&xr[t * 4] = *(const float4*)&xn[(size_t)tok * DIM + t * 4];
    __syncthreads();

    int w = t >> 5, lane = t & 31;
    float ab = 0.f, aa = 0.f;
    #pragma unroll 4
    for (int d = lane; d < DIM; d += 32) {
        float xv = xr[d];
        ab = fmaf(xv, wb[d * NH + w], ab);
        aa = fmaf(xv, wg[d * NH + w], aa);
    }
    #pragma unroll
    for (int o = 16; o > 0; o >>= 1) {
        ab += __shfl_xor_sync(0xffffffffu, ab, o);
        aa += __shfl_xor_sync(0xffffffffu, aa, o);
    }
    if (lane == 0) {
        beta[tok * NH + w] = 1.0f / (1.0f + expf(-ab));
        alph[tok * NH + w] = 1.0f / (1.0f + expf(-aa));
    }
}

// ---------------- activations: silu + per-head l2norm on q,k; silu on v ----
__global__ __launch_bounds__(128) void act_kernel(float* __restrict__ q,
                                                  float* __restrict__ k,
                                                  float* __restrict__ v)
{
    int tok = blockIdx.x, h = blockIdx.y, t = threadIdx.x;
    size_t idx = (size_t)tok * DIM + h * DH + t;
    float qv = q[idx], kv = k[idx], vv = v[idx];
    float qs = qv / (1.0f + expf(-qv));
    float ks = kv / (1.0f + expf(-kv));
    float vs = vv / (1.0f + expf(-vv));

    float a = qs * qs, b = ks * ks;
    #pragma unroll
    for (int o = 16; o > 0; o >>= 1) {
        a += __shfl_xor_sync(0xffffffffu, a, o);
        b += __shfl_xor_sync(0xffffffffu, b, o);
    }
    __shared__ float sq[4], sk[4];
    int w = t >> 5;
    if ((t & 31) == 0) { sq[w] = a; sk[w] = b; }
    __syncthreads();
    float qsum = sq[0] + sq[1] + sq[2] + sq[3];
    float ksum = sk[0] + sk[1] + sk[2] + sk[3];

    q[idx] = qs * rsqrtf(qsum + 1e-6f);
    k[idx] = ks * rsqrtf(ksum + 1e-6f);
    v[idx] = vs;
}

// ---------------- gated delta-rule scan, 4-way k-split ---------------------
// 64 blocks = (bh) x (column-group). 4-deep staging buffers: one
// __syncthreads per TWO timesteps (fast warps write bufs (t+2,t+3)&3 while
// laggards read (t,t+1)&3 — disjoint mod 4, no overlap).
__global__ __launch_bounds__(128) void scan_kernel(const float* __restrict__ q,
                                                   const float* __restrict__ k,
                                                   const float* __restrict__ v,
                                                   const float* __restrict__ beta,
                                                   const float* __restrict__ alph,
                                                   const float* __restrict__ state_in,
                                                   __half* __restrict__ attn_h,
                                                   float* __restrict__ state_out)
{
    int blk = blockIdx.x;
    int bh  = blk >> 2;
    int grp = blk & 3;
    int b = bh >> 3, h = bh & 7;
    int tid = threadIdx.x;
    int w = tid >> 5, lane = tid & 31;
    int colL  = w * 8 + (lane & 7);   // 0..31
    int seg   = lane >> 3;            // 0..3
    int vcol  = grp * 32 + colL;      // global state column
    int rbase = seg * 32;             // this thread's k-row range

    float S[32];
    const float* st = state_in + (size_t)bh * DH * DH;
    #pragma unroll
    for (int i = 0; i < 32; ++i) S[i] = st[(rbase + i) * DH + vcol];

    __shared__ __align__(16) float sk[4][DH];
    __shared__ __align__(16) float sq[4][DH];

    size_t base0 = (size_t)(b * TT) * DIM + h * DH;
    // prefetch t=0 and t=1
    float k0c = k[base0 + tid],        q0c = q[base0 + tid],        v0c = v[base0 + vcol];
    float k1c = k[base0 + DIM + tid],  q1c = q[base0 + DIM + tid],  v1c = v[base0 + DIM + vcol];
    float b0c = beta[(b * TT) * NH + h],     a0c = alph[(b * TT) * NH + h];
    float b1c = beta[(b * TT + 1) * NH + h], a1c = alph[(b * TT + 1) * NH + h];

    for (int t = 0; t < TT; t += 2) {
        int tok = b * TT + t;
        size_t base = (size_t)tok * DIM + h * DH;
        int u0 = t & 3, u1 = u0 + 1;
        sk[u0][tid] = k0c;  sq[u0][tid] = q0c;
        sk[u1][tid] = k1c;  sq[u1][tid] = q1c;
        float vv0 = v0c, bt0 = b0c, at0 = a0c;
        float vv1 = v1c, bt1 = b1c, at1 = a1c;
        __syncthreads();

        if (t + 2 < TT) {   // prefetch t+2, t+3 (overlaps compute)
            size_t nb = base + 2 * (size_t)DIM;
            k0c = k[nb + tid];        q0c = q[nb + tid];        v0c = v[nb + vcol];
            k1c = k[nb + DIM + tid];  q1c = q[nb + DIM + tid];  v1c = v[nb + DIM + vcol];
            b0c = beta[(tok + 2) * NH + h];  a0c = alph[(tok + 2) * NH + h];
            b1c = beta[(tok + 3) * NH + h];  a1c = alph[(tok + 3) * NH + h];
        }

        #pragma unroll
        for (int half_ = 0; half_ < 2; ++half_) {
            int ub = half_ ? u1 : u0;
            float vv = half_ ? vv1 : vv0;
            float bt = half_ ? bt1 : bt0;
            float at = half_ ? at1 : at0;
            size_t obase = base + half_ * (size_t)DIM;

            float p0 = 0.f, p1 = 0.f, p2 = 0.f, p3 = 0.f;
            #pragma unroll
            for (int i = 0; i < 32; i += 4) {
                float4 k4 = *(const float4*)&sk[ub][rbase + i];
                p0 = fmaf(k4.x, S[i + 0], p0);
                p1 = fmaf(k4.y, S[i + 1], p1);
                p2 = fmaf(k4.z, S[i + 2], p2);
                p3 = fmaf(k4.w, S[i + 3], p3);
            }
            float pred = (p0 + p1) + (p2 + p3);
            pred += __shfl_xor_sync(0xffffffffu, pred, 8);
            pred += __shfl_xor_sync(0xffffffffu, pred, 16);
            float dv = bt * (vv - at * pred);

            float o0 = 0.f, o1 = 0.f, o2 = 0.f, o3 = 0.f;
            #pragma unroll
            for (int i = 0; i < 32; i += 4) {
                float4 k4 = *(const float4*)&sk[ub][rbase + i];
                float4 q4 = *(const float4*)&sq[ub][rbase + i];
                float s0 = fmaf(k4.x, dv, at * S[i + 0]); S[i + 0] = s0; o0 = fmaf(q4.x, s0, o0);
                float s1 = fmaf(k4.y, dv, at * S[i + 1]); S[i + 1] = s1; o1 = fmaf(q4.y, s1, o1);
                float s2 = fmaf(k4.z, dv, at * S[i + 2]); S[i + 2] = s2; o2 = fmaf(q4.z, s2, o2);
                float s3 = fmaf(k4.w, dv, at * S[i + 3]); S[i + 3] = s3; o3 = fmaf(q4.w, s3, o3);
            }
            float o = (o0 + o1) + (o2 + o3);
            o += __shfl_xor_sync(0xffffffffu, o, 8);
            o += __shfl_xor_sync(0xffffffffu, o, 16);
            if (seg == 0) attn_h[obase + vcol] = __float2half_rn(o);
        }
    }

    float* so = state_out + (size_t)bh * DH * DH;
    #pragma unroll
    for (int i = 0; i < 32; ++i) so[(rbase + i) * DH + vcol] = S[i];
}

// ---------------- swiglu: hg_h = half(silu(hg) * hu) -----------------------
__global__ __launch_bounds__(256) void swiglu_kernel(const float* __restrict__ hg,
                                                     const float* __restrict__ hu,
                                                     __half* __restrict__ hg_h)
{
    size_t n = (size_t)BT * FF;
    for (size_t i = (size_t)blockIdx.x * blockDim.x + threadIdx.x; i < n;
         i += (size_t)gridDim.x * blockDim.x) {
        float g = hg[i];
        hg_h[i] = __float2half_rn((g / (1.0f + expf(-g))) * hu[i]);
    }
}

// ---------------- launch --------------------------------------------------
extern "C" void kernel_launch(void* const* d_in, const int* in_sizes, int n_in,
                              void* d_out, int out_size)
{
    const float* x     = (const float*)d_in[0];
    const float* state = (const float*)d_in[1];
    const float* wq    = (const float*)d_in[2];
    const float* wk    = (const float*)d_in[3];
    const float* wv    = (const float*)d_in[4];
    const float* wb    = (const float*)d_in[5];
    const float* wg    = (const float*)d_in[6];
    const float* wo    = (const float*)d_in[7];
    const float* wgate = (const float*)d_in[8];
    const float* wup   = (const float*)d_in[9];
    const float* wdown = (const float*)d_in[10];
    float* out = (float*)d_out;

    float *xn, *q, *k, *v, *beta, *alph, *x1, *xn2, *hg, *hu;
    __half *xn_h, *xn2_h, *attn_h, *hg_h;
    __half *wq_h, *wk_h, *wv_h, *wo_h, *wga_h, *wup_h, *wdn_h;
    cudaGetSymbolAddress((void**)&xn,    g_xn);
    cudaGetSymbolAddress((void**)&q,     g_q);
    cudaGetSymbolAddress((void**)&k,     g_k);
    cudaGetSymbolAddress((void**)&v,     g_v);
    cudaGetSymbolAddress((void**)&beta,  g_beta);
    cudaGetSymbolAddress((void**)&alph,  g_alph);
    cudaGetSymbolAddress((void**)&x1,    g_x1);
    cudaGetSymbolAddress((void**)&xn2,   g_xn2);
    cudaGetSymbolAddress((void**)&hg,    g_hg);
    cudaGetSymbolAddress((void**)&hu,    g_hu);
    cudaGetSymbolAddress((void**)&xn_h,  g_xn_h);
    cudaGetSymbolAddress((void**)&xn2_h, g_xn2_h);
    cudaGetSymbolAddress((void**)&attn_h,g_attn_h);
    cudaGetSymbolAddress((void**)&hg_h,  g_hg_h);
    cudaGetSymbolAddress((void**)&wq_h,  g_wq_h);
    cudaGetSymbolAddress((void**)&wk_h,  g_wk_h);
    cudaGetSymbolAddress((void**)&wv_h,  g_wv_h);
    cudaGetSymbolAddress((void**)&wo_h,  g_wo_h);
    cudaGetSymbolAddress((void**)&wga_h, g_wga_h);
    cudaGetSymbolAddress((void**)&wup_h, g_wup_h);
    cudaGetSymbolAddress((void**)&wdn_h, g_wdn_h);

    cudaFuncSetAttribute(gemm_h_kernel,
                         cudaFuncAttributeMaxDynamicSharedMemorySize, GEMM_SMEM);

    dim3 tb(32, 8);
    dim3 gD(DIM / 128, BT / 128);   // N=1024 GEMMs: 8 x 32
    dim3 gF(FF / 128,  BT / 128);   // N=4096 GEMMs: 32 x 32

    // 0) weight transpose+half conversions: [K][N] fp32 -> [N][K] half
    conv_tr_kernel<<<dim3(DIM/32, DIM/32), tb>>>(wq,    wq_h,  DIM, DIM);
    conv_tr_kernel<<<dim3(DIM/32, DIM/32), tb>>>(wk,    wk_h,  DIM, DIM);
    conv_tr_kernel<<<dim3(DIM/32, DIM/32), tb>>>(wv,    wv_h,  DIM, DIM);
    conv_tr_kernel<<<dim3(DIM/32, DIM/32), tb>>>(wo,    wo_h,  DIM, DIM);
    conv_tr_kernel<<<dim3(FF/32,  DIM/32), tb>>>(wgate, wga_h, DIM, FF);
    conv_tr_kernel<<<dim3(FF/32,  DIM/32), tb>>>(wup,   wup_h, DIM, FF);
    conv_tr_kernel<<<dim3(DIM/32, FF/32),  tb>>>(wdown, wdn_h, FF, DIM);

    // 1) xn = rmsnorm(x)  (fp32 + half)
    rmsnorm_kernel<<<BT, 256>>>(x, xn, xn_h);
    // 2) projections
    gemm_h_kernel<<<gD, 256, GEMM_SMEM>>>(xn_h, wq_h, nullptr, q, BT, DIM, DIM);
    gemm_h_kernel<<<gD, 256, GEMM_SMEM>>>(xn_h, wk_h, nullptr, k, BT, DIM, DIM);
    gemm_h_kernel<<<gD, 256, GEMM_SMEM>>>(xn_h, wv_h, nullptr, v, BT, DIM, DIM);
    ba_kernel<<<BT, 256>>>(xn, wb, wg, beta, alph);
    // 3) silu + l2norm (q,k), silu (v)
    act_kernel<<<dim3(BT, NH), 128>>>(q, k, v);
    // 4) recurrent scan; attn (half) + final state into d_out tail
    scan_kernel<<<NB * NH * 4, 128>>>(q, k, v, beta, alph, state,
                                      attn_h, out + (size_t)BT * DIM);
    // 5) x1 = x + attn @ wo
    gemm_h_kernel<<<gD, 256, GEMM_SMEM>>>(attn_h, wo_h, x, x1, BT, DIM, DIM);
    // 6) xn2 = rmsnorm(x1)
    rmsnorm_kernel<<<BT, 256>>>(x1, xn2, xn2_h);
    // 7) mlp
    gemm_h_kernel<<<gF, 256, GEMM_SMEM>>>(xn2_h, wga_h, nullptr, hg, BT, FF, DIM);
    gemm_h_kernel<<<gF, 256, GEMM_SMEM>>>(xn2_h, wup_h, nullptr, hu, BT, FF, DIM);
    swiglu_kernel<<<2048, 256>>>(hg, hu, hg_h);
    // 8) out = x1 + hg @ wdown
    gemm_h_kernel<<<gD, 256, GEMM_SMEM>>>(hg_h, wdn_h, x1, out, BT, DIM, FF);
}

// round 7
// speedup vs baseline: 4.1670x; 1.0814x over previous
#include <cuda_runtime.h>
#include <cuda_fp16.h>
#include <math.h>
#include <stdint.h>

// Problem dims (fixed by the dataset)
#define BT  4096     // B*T tokens
#define DIM 1024     // model dim
#define FF  4096     // mlp dim
#define NH  8        // heads
#define DH  128      // head dim
#define NB  2        // batch
#define TT  2048     // seq len

// ---------------- scratch (device globals; no allocation allowed) ----------
__device__ float  g_xn  [BT * DIM];
__device__ float  g_q   [BT * DIM];
__device__ float  g_k   [BT * DIM];
__device__ float  g_v   [BT * DIM];
__device__ float  g_beta[BT * NH];
__device__ float  g_alph[BT * NH];
__device__ float  g_x1  [BT * DIM];
__device__ float  g_xn2 [BT * DIM];
__device__ float  g_hu  [BT * FF];
__device__ float  g_hg  [BT * FF];
// half copies (GEMM operands); weights stored TRANSPOSED [N][K]
__device__ __half g_xn_h  [BT * DIM];
__device__ __half g_xn2_h [BT * DIM];
__device__ __half g_attn_h[BT * DIM];
__device__ __half g_hg_h  [BT * FF];
__device__ __half g_wq_h  [DIM * DIM];
__device__ __half g_wk_h  [DIM * DIM];
__device__ __half g_wv_h  [DIM * DIM];
__device__ __half g_wo_h  [DIM * DIM];
__device__ __half g_wga_h [DIM * FF];
__device__ __half g_wup_h [DIM * FF];
__device__ __half g_wdn_h [FF * DIM];

// ---------------- transpose + fp32->half: in[K][N] -> out[N][K] ------------
__global__ __launch_bounds__(256) void conv_tr_kernel(const float* __restrict__ in,
                                                      __half* __restrict__ out,
                                                      int K, int N)
{
    __shared__ float s[32][33];
    int bx = blockIdx.x * 32;  // n base
    int by = blockIdx.y * 32;  // k base
    int tx = threadIdx.x, ty = threadIdx.y;
    #pragma unroll
    for (int j = 0; j < 4; ++j)
        s[ty + 8 * j][tx] = in[(size_t)(by + ty + 8 * j) * N + bx + tx];
    __syncthreads();
    #pragma unroll
    for (int j = 0; j < 4; ++j)
        out[(size_t)(bx + ty + 8 * j) * K + by + tx] = __float2half_rn(s[tx][ty + 8 * j]);
}

// ---------------- rmsnorm: fp32 out + half out -----------------------------
__global__ __launch_bounds__(256) void rmsnorm_kernel(const float* __restrict__ in,
                                                      float* __restrict__ out,
                                                      __half* __restrict__ out_h)
{
    int row = blockIdx.x;
    int i   = threadIdx.x * 4;
    const float* r = in + (size_t)row * DIM;
    float4 xv = *(const float4*)&r[i];
    float ss = xv.x*xv.x + xv.y*xv.y + xv.z*xv.z + xv.w*xv.w;

    #pragma unroll
    for (int o = 16; o > 0; o >>= 1) ss += __shfl_xor_sync(0xffffffffu, ss, o);
    __shared__ float sbuf[8];
    int w = threadIdx.x >> 5;
    if ((threadIdx.x & 31) == 0) sbuf[w] = ss;
    __syncthreads();
    float tot = sbuf[0]+sbuf[1]+sbuf[2]+sbuf[3]+sbuf[4]+sbuf[5]+sbuf[6]+sbuf[7];
    float scale = rsqrtf(tot * (1.0f / DIM) + 1e-6f);

    float4 ov;
    ov.x = xv.x*scale; ov.y = xv.y*scale; ov.z = xv.z*scale; ov.w = xv.w*scale;
    size_t off = (size_t)row * DIM + i;
    *(float4*)&out[off] = ov;
    __half2 h0 = __floats2half2_rn(ov.x, ov.y);
    __half2 h1 = __floats2half2_rn(ov.z, ov.w);
    *(__half2*)&out_h[off]     = h0;
    *(__half2*)&out_h[off + 2] = h1;
}

// ---------------- FP16 tensor-core GEMM, cp.async + ldmatrix ---------------
// C[M,N] = A[M,K] @ Bt[N,K]^T (+Res), fp32 accumulate/out.
// BM=128, BN=128, BK=64; 256 threads = 8 warps 2(m)x4(n); warp tile 64x32.

#define AST_H 72                    // smem row stride in halves (144B)
#define A_STG (128 * AST_H)         // 9216 halves per stage
#define GEMM_SMEM (4 * A_STG * 2)   // 73728 bytes (2 stages A + 2 stages B)

__device__ __forceinline__ void cp16(uint32_t smem_dst, const void* gsrc) {
    asm volatile("cp.async.cg.shared.global [%0], [%1], 16;" :: "r"(smem_dst), "l"(gsrc));
}

__device__ __forceinline__ void ldm4(uint32_t& r0, uint32_t& r1, uint32_t& r2,
                                     uint32_t& r3, const __half* p) {
    uint32_t a = (uint32_t)__cvta_generic_to_shared(p);
    asm volatile("ldmatrix.sync.aligned.m8n8.x4.shared.b16 {%0,%1,%2,%3}, [%4];"
                 : "=r"(r0), "=r"(r1), "=r"(r2), "=r"(r3) : "r"(a));
}

__global__ __launch_bounds__(256, 2) void gemm_h_kernel(const __half* __restrict__ A,
                                                        const __half* __restrict__ Bt,
                                                        const float* __restrict__ Res,
                                                        float* __restrict__ C,
                                                        int M, int N, int K)
{
    extern __shared__ __align__(16) __half sm[];
    __half* As = sm;                  // [2][A_STG]
    __half* Bs = sm + 2 * A_STG;      // [2][A_STG]

    int tid  = threadIdx.x;
    int lane = tid & 31;
    int warp = tid >> 5;
    int g    = lane >> 2;     // 0..7
    int t4   = lane & 3;      // 0..3
    int wm   = warp & 1;
    int wn   = warp >> 1;
    int bm   = blockIdx.y * 128;
    int bn   = blockIdx.x * 128;

    int cRow  = tid >> 1;            // 0..127
    int cBase = (tid & 1) * 4;       // 16B-chunk base (0 or 4)

    // ldmatrix lane-address components
    int lm8   = lane & 7;
    int lmHi  = (lane >> 4);         // 0/1
    int lmMid = (lane >> 3) & 1;     // 0/1

    float acc[4][4][4];
    #pragma unroll
    for (int i = 0; i < 4; ++i)
        #pragma unroll
        for (int j = 0; j < 4; ++j)
            #pragma unroll
            for (int c = 0; c < 4; ++c) acc[i][j][c] = 0.f;

    int nIter = K >> 6;

    auto copy_stage = [&](int it, int stg) {
        int k0 = it << 6;
        #pragma unroll
        for (int i = 0; i < 4; ++i) {
            int c = cBase + i;       // 16B chunk = 8 halves
            uint32_t da = (uint32_t)__cvta_generic_to_shared(&As[stg * A_STG + cRow * AST_H + c * 8]);
            cp16(da, &A[(size_t)(bm + cRow) * K + k0 + c * 8]);
            uint32_t db = (uint32_t)__cvta_generic_to_shared(&Bs[stg * A_STG + cRow * AST_H + c * 8]);
            cp16(db, &Bt[(size_t)(bn + cRow) * K + k0 + c * 8]);
        }
        asm volatile("cp.async.commit_group;");
    };

    copy_stage(0, 0);

    for (int it = 0; it < nIter; ++it) {
        if (it + 1 < nIter) {
            copy_stage(it + 1, (it + 1) & 1);
            asm volatile("cp.async.wait_group 1;");
        } else {
            asm volatile("cp.async.wait_group 0;");
        }
        __syncthreads();

        const __half* Ac = As + (it & 1) * A_STG;
        const __half* Bc = Bs + (it & 1) * A_STG;

        #pragma unroll
        for (int kc = 0; kc < 64; kc += 16) {
            // B fragments: one x4 covers 2 n-tiles (tiles: n+0/k, n+0/k+8, n+8/k, n+8/k+8)
            uint32_t bf[4][2];
            #pragma unroll
            for (int ntp = 0; ntp < 2; ++ntp) {
                int brow = wn * 32 + ntp * 16 + (lmHi << 3) + lm8;
                int bk   = kc + (lmMid << 3);
                ldm4(bf[2*ntp][0], bf[2*ntp][1], bf[2*ntp+1][0], bf[2*ntp+1][1],
                     &Bc[brow * AST_H + bk]);
            }
            #pragma unroll
            for (int mt = 0; mt < 4; ++mt) {
                // A x4 tiles: m+0/k, m+8/k, m+0/k+8, m+8/k+8
                int arow = wm * 64 + mt * 16 + (lmMid << 3) + lm8;
                int ak   = kc + (lmHi << 3);
                uint32_t a0, a1, a2, a3;
                ldm4(a0, a1, a2, a3, &Ac[arow * AST_H + ak]);
                #pragma unroll
                for (int nt = 0; nt < 4; ++nt) {
                    asm volatile(
                        "mma.sync.aligned.m16n8k16.row.col.f32.f16.f16.f32 "
                        "{%0,%1,%2,%3}, {%4,%5,%6,%7}, {%8,%9}, {%0,%1,%2,%3};"
                        : "+f"(acc[mt][nt][0]), "+f"(acc[mt][nt][1]),
                          "+f"(acc[mt][nt][2]), "+f"(acc[mt][nt][3])
                        : "r"(a0), "r"(a1), "r"(a2), "r"(a3),
                          "r"(bf[nt][0]), "r"(bf[nt][1]));
                }
            }
        }
        __syncthreads();
    }

    #pragma unroll
    for (int mt = 0; mt < 4; ++mt) {
        #pragma unroll
        for (int nt = 0; nt < 4; ++nt) {
            int row = bm + wm * 64 + mt * 16 + g;
            int col = bn + wn * 32 + nt * 8 + 2 * t4;
            size_t o0 = (size_t)row * N + col;
            size_t o1 = (size_t)(row + 8) * N + col;
            float2 u, l;
            u.x = acc[mt][nt][0]; u.y = acc[mt][nt][1];
            l.x = acc[mt][nt][2]; l.y = acc[mt][nt][3];
            if (Res) {
                float2 r0 = *(const float2*)&Res[o0];
                float2 r1 = *(const float2*)&Res[o1];
                u.x += r0.x; u.y += r0.y;
                l.x += r1.x; l.y += r1.y;
            }
            *(float2*)&C[o0] = u;
            *(float2*)&C[o1] = l;
        }
    }
}

// ---------------- beta/alpha: sigmoid(xn @ wb), sigmoid(xn @ wg) -----------
__global__ __launch_bounds__(256) void ba_kernel(const float* __restrict__ xn,
                                                 const float* __restrict__ wb,
                                                 const float* __restrict__ wg,
                                                 float* __restrict__ beta,
                                                 float* __restrict__ alph)
{
    __shared__ __align__(16) float xr[DIM];
    int tok = blockIdx.x;
    int t = threadIdx.x;
    *(float4*)&xr[t * 4] = *(const float4*)&xn[(size_t)tok * DIM + t * 4];
    __syncthreads();

    int w = t >> 5, lane = t & 31;
    float ab = 0.f, aa = 0.f;
    #pragma unroll 4
    for (int d = lane; d < DIM; d += 32) {
        float xv = xr[d];
        ab = fmaf(xv, wb[d * NH + w], ab);
        aa = fmaf(xv, wg[d * NH + w], aa);
    }
    #pragma unroll
    for (int o = 16; o > 0; o >>= 1) {
        ab += __shfl_xor_sync(0xffffffffu, ab, o);
        aa += __shfl_xor_sync(0xffffffffu, aa, o);
    }
    if (lane == 0) {
        beta[tok * NH + w] = 1.0f / (1.0f + expf(-ab));
        alph[tok * NH + w] = 1.0f / (1.0f + expf(-aa));
    }
}

// ---------------- activations: silu + per-head l2norm on q,k; silu on v ----
__global__ __launch_bounds__(128) void act_kernel(float* __restrict__ q,
                                                  float* __restrict__ k,
                                                  float* __restrict__ v)
{
    int tok = blockIdx.x, h = blockIdx.y, t = threadIdx.x;
    size_t idx = (size_t)tok * DIM + h * DH + t;
    float qv = q[idx], kv = k[idx], vv = v[idx];
    float qs = qv / (1.0f + expf(-qv));
    float ks = kv / (1.0f + expf(-kv));
    float vs = vv / (1.0f + expf(-vv));

    float a = qs * qs, b = ks * ks;
    #pragma unroll
    for (int o = 16; o > 0; o >>= 1) {
        a += __shfl_xor_sync(0xffffffffu, a, o);
        b += __shfl_xor_sync(0xffffffffu, b, o);
    }
    __shared__ float sq[4], sk[4];
    int w = t >> 5;
    if ((t & 31) == 0) { sq[w] = a; sk[w] = b; }
    __syncthreads();
    float qsum = sq[0] + sq[1] + sq[2] + sq[3];
    float ksum = sk[0] + sk[1] + sk[2] + sk[3];

    q[idx] = qs * rsqrtf(qsum + 1e-6f);
    k[idx] = ks * rsqrtf(ksum + 1e-6f);
    v[idx] = vs;
}

// ---------------- gated delta-rule scan, 8-way k-split ---------------------
// 128 blocks = (bh 0..15) x (column-group 0..7; 16 columns each).
// Thread (warp w, lane l): column colL = w*4 + (l&3), k-segment seg = l>>2
// (16 rows). Dot-product reduction via shfl xor 4/8/16. 4-deep staging
// buffers: one __syncthreads per TWO timesteps (writers use bufs
// (t+2,t+3)&3, readers (t,t+1)&3 — disjoint mod 4).
__global__ __launch_bounds__(128) void scan_kernel(const float* __restrict__ q,
                                                   const float* __restrict__ k,
                                                   const float* __restrict__ v,
                                                   const float* __restrict__ beta,
                                                   const float* __restrict__ alph,
                                                   const float* __restrict__ state_in,
                                                   __half* __restrict__ attn_h,
                                                   float* __restrict__ state_out)
{
    int blk = blockIdx.x;
    int bh  = blk >> 3;
    int grp = blk & 7;
    int b = bh >> 3, h = bh & 7;
    int tid = threadIdx.x;
    int w = tid >> 5, lane = tid & 31;
    int colL  = w * 4 + (lane & 3);   // 0..15
    int seg   = lane >> 2;            // 0..7
    int vcol  = grp * 16 + colL;      // global state column
    int rbase = seg * 16;             // this thread's k-row range

    float S[16];
    const float* st = state_in + (size_t)bh * DH * DH;
    #pragma unroll
    for (int i = 0; i < 16; ++i) S[i] = st[(rbase + i) * DH + vcol];

    __shared__ __align__(16) float sk[4][DH];
    __shared__ __align__(16) float sq[4][DH];

    size_t base0 = (size_t)(b * TT) * DIM + h * DH;
    // prefetch t=0 and t=1
    float k0c = k[base0 + tid],        q0c = q[base0 + tid],        v0c = v[base0 + vcol];
    float k1c = k[base0 + DIM + tid],  q1c = q[base0 + DIM + tid],  v1c = v[base0 + DIM + vcol];
    float b0c = beta[(b * TT) * NH + h],     a0c = alph[(b * TT) * NH + h];
    float b1c = beta[(b * TT + 1) * NH + h], a1c = alph[(b * TT + 1) * NH + h];

    for (int t = 0; t < TT; t += 2) {
        int tok = b * TT + t;
        size_t base = (size_t)tok * DIM + h * DH;
        int u0 = t & 3, u1 = u0 + 1;
        sk[u0][tid] = k0c;  sq[u0][tid] = q0c;
        sk[u1][tid] = k1c;  sq[u1][tid] = q1c;
        float vv0 = v0c, bt0 = b0c, at0 = a0c;
        float vv1 = v1c, bt1 = b1c, at1 = a1c;
        __syncthreads();

        if (t + 2 < TT) {   // prefetch t+2, t+3 (overlaps compute)
            size_t nb = base + 2 * (size_t)DIM;
            k0c = k[nb + tid];        q0c = q[nb + tid];        v0c = v[nb + vcol];
            k1c = k[nb + DIM + tid];  q1c = q[nb + DIM + tid];  v1c = v[nb + DIM + vcol];
            b0c = beta[(tok + 2) * NH + h];  a0c = alph[(tok + 2) * NH + h];
            b1c = beta[(tok + 3) * NH + h];  a1c = alph[(tok + 3) * NH + h];
        }

        #pragma unroll
        for (int half_ = 0; half_ < 2; ++half_) {
            int ub = half_ ? u1 : u0;
            float vv = half_ ? vv1 : vv0;
            float bt = half_ ? bt1 : bt0;
            float at = half_ ? at1 : at0;
            size_t obase = base + half_ * (size_t)DIM;

            float p0 = 0.f, p1 = 0.f, p2 = 0.f, p3 = 0.f;
            #pragma unroll
            for (int i = 0; i < 16; i += 4) {
                float4 k4 = *(const float4*)&sk[ub][rbase + i];
                p0 = fmaf(k4.x, S[i + 0], p0);
                p1 = fmaf(k4.y, S[i + 1], p1);
                p2 = fmaf(k4.z, S[i + 2], p2);
                p3 = fmaf(k4.w, S[i + 3], p3);
            }
            float pred = (p0 + p1) + (p2 + p3);
            pred += __shfl_xor_sync(0xffffffffu, pred, 4);
            pred += __shfl_xor_sync(0xffffffffu, pred, 8);
            pred += __shfl_xor_sync(0xffffffffu, pred, 16);
            float dv = bt * (vv - at * pred);

            float o0 = 0.f, o1 = 0.f, o2 = 0.f, o3 = 0.f;
            #pragma unroll
            for (int i = 0; i < 16; i += 4) {
                float4 k4 = *(const float4*)&sk[ub][rbase + i];
                float4 q4 = *(const float4*)&sq[ub][rbase + i];
                float s0 = fmaf(k4.x, dv, at * S[i + 0]); S[i + 0] = s0; o0 = fmaf(q4.x, s0, o0);
                float s1 = fmaf(k4.y, dv, at * S[i + 1]); S[i + 1] = s1; o1 = fmaf(q4.y, s1, o1);
                float s2 = fmaf(k4.z, dv, at * S[i + 2]); S[i + 2] = s2; o2 = fmaf(q4.z, s2, o2);
                float s3 = fmaf(k4.w, dv, at * S[i + 3]); S[i + 3] = s3; o3 = fmaf(q4.w, s3, o3);
            }
            float o = (o0 + o1) + (o2 + o3);
            o += __shfl_xor_sync(0xffffffffu, o, 4);
            o += __shfl_xor_sync(0xffffffffu, o, 8);
            o += __shfl_xor_sync(0xffffffffu, o, 16);
            if (seg == 0) attn_h[obase + vcol] = __float2half_rn(o);
        }
    }

    float* so = state_out + (size_t)bh * DH * DH;
    #pragma unroll
    for (int i = 0; i < 16; ++i) so[(rbase + i) * DH + vcol] = S[i];
}

// ---------------- swiglu: hg_h = half(silu(hg) * hu) -----------------------
__global__ __launch_bounds__(256) void swiglu_kernel(const float* __restrict__ hg,
                                                     const float* __restrict__ hu,
                                                     __half* __restrict__ hg_h)
{
    size_t n = (size_t)BT * FF;
    for (size_t i = (size_t)blockIdx.x * blockDim.x + threadIdx.x; i < n;
         i += (size_t)gridDim.x * blockDim.x) {
        float g = hg[i];
        hg_h[i] = __float2half_rn((g / (1.0f + expf(-g))) * hu[i]);
    }
}

// ---------------- launch --------------------------------------------------
extern "C" void kernel_launch(void* const* d_in, const int* in_sizes, int n_in,
                              void* d_out, int out_size)
{
    const float* x     = (const float*)d_in[0];
    const float* state = (const float*)d_in[1];
    const float* wq    = (const float*)d_in[2];
    const float* wk    = (const float*)d_in[3];
    const float* wv    = (const float*)d_in[4];
    const float* wb    = (const float*)d_in[5];
    const float* wg    = (const float*)d_in[6];
    const float* wo    = (const float*)d_in[7];
    const float* wgate = (const float*)d_in[8];
    const float* wup   = (const float*)d_in[9];
    const float* wdown = (const float*)d_in[10];
    float* out = (float*)d_out;

    float *xn, *q, *k, *v, *beta, *alph, *x1, *xn2, *hg, *hu;
    __half *xn_h, *xn2_h, *attn_h, *hg_h;
    __half *wq_h, *wk_h, *wv_h, *wo_h, *wga_h, *wup_h, *wdn_h;
    cudaGetSymbolAddress((void**)&xn,    g_xn);
    cudaGetSymbolAddress((void**)&q,     g_q);
    cudaGetSymbolAddress((void**)&k,     g_k);
    cudaGetSymbolAddress((void**)&v,     g_v);
    cudaGetSymbolAddress((void**)&beta,  g_beta);
    cudaGetSymbolAddress((void**)&alph,  g_alph);
    cudaGetSymbolAddress((void**)&x1,    g_x1);
    cudaGetSymbolAddress((void**)&xn2,   g_xn2);
    cudaGetSymbolAddress((void**)&hg,    g_hg);
    cudaGetSymbolAddress((void**)&hu,    g_hu);
    cudaGetSymbolAddress((void**)&xn_h,  g_xn_h);
    cudaGetSymbolAddress((void**)&xn2_h, g_xn2_h);
    cudaGetSymbolAddress((void**)&attn_h,g_attn_h);
    cudaGetSymbolAddress((void**)&hg_h,  g_hg_h);
    cudaGetSymbolAddress((void**)&wq_h,  g_wq_h);
    cudaGetSymbolAddress((void**)&wk_h,  g_wk_h);
    cudaGetSymbolAddress((void**)&wv_h,  g_wv_h);
    cudaGetSymbolAddress((void**)&wo_h,  g_wo_h);
    cudaGetSymbolAddress((void**)&wga_h, g_wga_h);
    cudaGetSymbolAddress((void**)&wup_h, g_wup_h);
    cudaGetSymbolAddress((void**)&wdn_h, g_wdn_h);

    cudaFuncSetAttribute(gemm_h_kernel,
                         cudaFuncAttributeMaxDynamicSharedMemorySize, GEMM_SMEM);

    dim3 tb(32, 8);
    dim3 gD(DIM / 128, BT / 128);   // N=1024 GEMMs: 8 x 32
    dim3 gF(FF / 128,  BT / 128);   // N=4096 GEMMs: 32 x 32

    // 0) weight transpose+half conversions: [K][N] fp32 -> [N][K] half
    conv_tr_kernel<<<dim3(DIM/32, DIM/32), tb>>>(wq,    wq_h,  DIM, DIM);
    conv_tr_kernel<<<dim3(DIM/32, DIM/32), tb>>>(wk,    wk_h,  DIM, DIM);
    conv_tr_kernel<<<dim3(DIM/32, DIM/32), tb>>>(wv,    wv_h,  DIM, DIM);
    conv_tr_kernel<<<dim3(DIM/32, DIM/32), tb>>>(wo,    wo_h,  DIM, DIM);
    conv_tr_kernel<<<dim3(FF/32,  DIM/32), tb>>>(wgate, wga_h, DIM, FF);
    conv_tr_kernel<<<dim3(FF/32,  DIM/32), tb>>>(wup,   wup_h, DIM, FF);
    conv_tr_kernel<<<dim3(DIM/32, FF/32),  tb>>>(wdown, wdn_h, FF, DIM);

    // 1) xn = rmsnorm(x)  (fp32 + half)
    rmsnorm_kernel<<<BT, 256>>>(x, xn, xn_h);
    // 2) projections
    gemm_h_kernel<<<gD, 256, GEMM_SMEM>>>(xn_h, wq_h, nullptr, q, BT, DIM, DIM);
    gemm_h_kernel<<<gD, 256, GEMM_SMEM>>>(xn_h, wk_h, nullptr, k, BT, DIM, DIM);
    gemm_h_kernel<<<gD, 256, GEMM_SMEM>>>(xn_h, wv_h, nullptr, v, BT, DIM, DIM);
    ba_kernel<<<BT, 256>>>(xn, wb, wg, beta, alph);
    // 3) silu + l2norm (q,k), silu (v)
    act_kernel<<<dim3(BT, NH), 128>>>(q, k, v);
    // 4) recurrent scan; attn (half) + final state into d_out tail
    scan_kernel<<<NB * NH * 8, 128>>>(q, k, v, beta, alph, state,
                                      attn_h, out + (size_t)BT * DIM);
    // 5) x1 = x + attn @ wo
    gemm_h_kernel<<<gD, 256, GEMM_SMEM>>>(attn_h, wo_h, x, x1, BT, DIM, DIM);
    // 6) xn2 = rmsnorm(x1)
    rmsnorm_kernel<<<BT, 256>>>(x1, xn2, xn2_h);
    // 7) mlp
    gemm_h_kernel<<<gF, 256, GEMM_SMEM>>>(xn2_h, wga_h, nullptr, hg, BT, FF, DIM);
    gemm_h_kernel<<<gF, 256, GEMM_SMEM>>>(xn2_h, wup_h, nullptr, hu, BT, FF, DIM);
    swiglu_kernel<<<2048, 256>>>(hg, hu, hg_h);
    // 8) out = x1 + hg @ wdown
    gemm_h_kernel<<<gD, 256, GEMM_SMEM>>>(hg_h, wdn_h, x1, out, BT, DIM, FF);
}